// round 13
// baseline (speedup 1.0000x reference)
#include <cuda_runtime.h>
#include <cuda_bf16.h>

// Problem constants
#define BATCH   2
#define SEQ     2048
#define DMODEL  1024
#define NHEAD   16
#define DK      64
#define MROWS   (BATCH * SEQ)       // 4096
#define DM2     (DMODEL / 2)        // u32 (bf16x2) per row
#define WU4     (DMODEL * DMODEL / 8)  // uint4 per weight matrix (131072)

// ---------------------------------------------------------------------------
// Scratch: everything pre-split as bf16 hi/lo (u32 = bf16x2 pair)
// ---------------------------------------------------------------------------
__device__ unsigned g_Qh[MROWS * DM2], g_Ql[MROWS * DM2];
__device__ unsigned g_Kh[MROWS * DM2], g_Kl[MROWS * DM2];
__device__ unsigned g_Vh[MROWS * DM2], g_Vl[MROWS * DM2];
__device__ unsigned g_Xh[MROWS * DM2], g_Xl[MROWS * DM2];
__device__ unsigned g_Wh[4 * DMODEL * DM2], g_Wl[4 * DMODEL * DM2];

// ---------------------------------------------------------------------------
// Warp-level tensor core helpers (sm_80-baseline PTX: works on plain sm_103)
// ---------------------------------------------------------------------------
__device__ __forceinline__ unsigned smem_u32(const void* p) {
    return (unsigned)__cvta_generic_to_shared(p);
}
__device__ __forceinline__ void ldmx4(unsigned* r, unsigned addr) {
    asm volatile(
        "ldmatrix.sync.aligned.m8n8.x4.shared.b16 {%0,%1,%2,%3}, [%4];"
        : "=r"(r[0]), "=r"(r[1]), "=r"(r[2]), "=r"(r[3]) : "r"(addr));
}
__device__ __forceinline__ void ldmx4t(unsigned* r, unsigned addr) {
    asm volatile(
        "ldmatrix.sync.aligned.m8n8.x4.trans.shared.b16 {%0,%1,%2,%3}, [%4];"
        : "=r"(r[0]), "=r"(r[1]), "=r"(r[2]), "=r"(r[3]) : "r"(addr));
}
__device__ __forceinline__ void mma_bf16(float* d, const unsigned* a,
                                         unsigned b0, unsigned b1) {
    asm volatile(
        "mma.sync.aligned.m16n8k16.row.col.f32.bf16.bf16.f32 "
        "{%0,%1,%2,%3}, {%4,%5,%6,%7}, {%8,%9}, {%0,%1,%2,%3};"
        : "+f"(d[0]), "+f"(d[1]), "+f"(d[2]), "+f"(d[3])
        : "r"(a[0]), "r"(a[1]), "r"(a[2]), "r"(a[3]), "r"(b0), "r"(b1));
}

// fp32 pair -> bf16x2 hi + bf16x2 lo
__device__ __forceinline__ void cvt_split2(float x0, float x1,
                                           unsigned& h, unsigned& l) {
    asm("cvt.rn.satfinite.bf16x2.f32 %0, %1, %2;" : "=r"(h) : "f"(x1), "f"(x0));
    float hf0 = __uint_as_float(h << 16);
    float hf1 = __uint_as_float(h & 0xffff0000u);
    float l0 = x0 - hf0;
    float l1 = x1 - hf1;
    asm("cvt.rn.satfinite.bf16x2.f32 %0, %1, %2;" : "=r"(l) : "f"(l1), "f"(l0));
}
__device__ __forceinline__ void split_store(float4 a, float4 b,
                                            char* dst_hi, char* dst_lo) {
    uint4 h, l;
    cvt_split2(a.x, a.y, h.x, l.x);
    cvt_split2(a.z, a.w, h.y, l.y);
    cvt_split2(b.x, b.y, h.z, l.z);
    cvt_split2(b.z, b.w, h.w, l.w);
    *(uint4*)dst_hi = h;
    *(uint4*)dst_lo = l;
}

// cp.async 16B (bypass-L1)
__device__ __forceinline__ void cp_async16(void* smem_ptr, const void* gptr) {
    unsigned saddr = (unsigned)__cvta_generic_to_shared(smem_ptr);
    asm volatile("cp.async.cg.shared.global [%0], [%1], 16;"
                 :: "r"(saddr), "l"(gptr) : "memory");
}
__device__ __forceinline__ void cp_commit() {
    asm volatile("cp.async.commit_group;" ::: "memory");
}
__device__ __forceinline__ void cp_wait0() {
    asm volatile("cp.async.wait_group 0;" ::: "memory");
}
__device__ __forceinline__ void cp_wait1() {
    asm volatile("cp.async.wait_group 1;" ::: "memory");
}

// ---------------------------------------------------------------------------
// Weight pre-split: w[1024x1024] fp32 -> hi/lo bf16x2 [1024][512] u32
// ---------------------------------------------------------------------------
__global__ void __launch_bounds__(256)
presplit_w(const float* __restrict__ w0, const float* __restrict__ w1,
           const float* __restrict__ w2, const float* __restrict__ w3) {
    const int m = blockIdx.y;
    const float* src = (m == 0) ? w0 : (m == 1) ? w1 : (m == 2) ? w2 : w3;
    const int gid = blockIdx.x * 256 + threadIdx.x;   // 0..131071
    const float4* s4 = (const float4*)src;
    float4 a = s4[2 * gid], b = s4[2 * gid + 1];
    uint4 h, l;
    cvt_split2(a.x, a.y, h.x, l.x);
    cvt_split2(a.z, a.w, h.y, l.y);
    cvt_split2(b.x, b.y, h.z, l.z);
    cvt_split2(b.z, b.w, h.w, l.w);
    ((uint4*)g_Wh)[(size_t)m * WU4 + gid] = h;
    ((uint4*)g_Wl)[(size_t)m * WU4 + gid] = l;
}

// ---------------------------------------------------------------------------
// Tensor-core NT GEMM: C[m,n] = sum_k A[m,k]*W[n,k]; CTA 128x128, 512 thr,
// 16 warps (4m x 4n, warp tile 32x32), K staged 64/stage, cp.async
// double-buffered (wait_group 1). B always pre-split (cp.async copy).
// PA: A pre-split (cp.async) else fp32 converted in-loop.
// SC: C written split bf16 hi/lo, else fp32.
// ---------------------------------------------------------------------------
#define GK_STAGES 16
#define GK_TILE_BYTES (128 * 64 * 2)            // 16 KB per tensor-half
#define GK_BUF_BYTES (4 * GK_TILE_BYTES)        // Ah, Al, Bh, Bl = 64 KB
#define GEMM_SMEM (2 * GK_BUF_BYTES + 1024)

template <bool PA, bool SC>
__device__ __forceinline__ void gemm_body(
    const float* __restrict__ A,
    const uint4* __restrict__ Ah4, const uint4* __restrict__ Al4,
    const uint4* __restrict__ Wh4, const uint4* __restrict__ Wl4,
    float* __restrict__ C,
    unsigned* __restrict__ Ch, unsigned* __restrict__ Cl) {
    extern __shared__ char dyn_raw[];
    char* dynb = (char*)(((unsigned long long)(size_t)dyn_raw + 1023ull) &
                         ~1023ull);
    const unsigned sbase = smem_u32(dynb);

    const int tid = threadIdx.x;
    const int wid = tid >> 5;
    const int lane = tid & 31;
    const int m0 = blockIdx.y * 128;
    const int n0 = blockIdx.x * 128;

    const float4* A4 = (const float4*)A;

    // fp32-A staging map: rows rb, rb+64; 16-float chunk cc
    const int rb = tid >> 3;      // 0..63
    const int cc = tid & 7;

    // warp tile
    const int wm = (wid >> 2) * 32;
    const int wn = (wid & 3) * 32;
    const int arow = lane & 15;
    const unsigned ahi = (unsigned)(lane >> 4);
    const unsigned axor = (unsigned)((arow & 7) << 4);
    const int brow = (lane & 7) + ((lane >> 4) << 3);
    const unsigned bxor = (unsigned)((brow & 7) << 4);
    const unsigned bhi = (unsigned)((lane >> 3) & 1);

    float d[2][4][4];
#pragma unroll
    for (int i = 0; i < 2; i++)
#pragma unroll
        for (int j = 0; j < 4; j++)
#pragma unroll
            for (int e = 0; e < 4; e++) d[i][j][e] = 0.0f;

    float4 ra[2][2];

#define GBUF(b) (dynb + (b) * GK_BUF_BYTES)

#define GK_LDGA(s)                                                         \
    do { if (!PA) {                                                        \
        _Pragma("unroll")                                                  \
        for (int i = 0; i < 2; i++) {                                      \
            const size_t ga =                                              \
                (size_t)(m0 + rb + 64 * i) * 256 + (s) * 16 + cc * 2;      \
            ra[i][0] = A4[ga];                                             \
            ra[i][1] = A4[ga + 1];                                         \
        } } } while (0)

#define GK_STSA(b)                                                         \
    do { if (!PA) {                                                        \
        char* Ahp = GBUF(b);                                               \
        char* Alp = Ahp + GK_TILE_BYTES;                                   \
        _Pragma("unroll")                                                  \
        for (int i = 0; i < 2; i++) {                                      \
            const int r = rb + 64 * i;                                     \
            const unsigned sw = (unsigned)(r * 128) +                      \
                (((unsigned)cc ^ (unsigned)(r & 7)) << 4);                 \
            split_store(ra[i][0], ra[i][1], Ahp + sw, Alp + sw);           \
        } } } while (0)

#define GK_CPA(s, b)                                                       \
    do { if (PA) {                                                         \
        _Pragma("unroll")                                                  \
        for (int t = 0; t < 2; t++) {                                      \
            const uint4* srcp = t ? Al4 : Ah4;                             \
            _Pragma("unroll")                                              \
            for (int i = 0; i < 2; i++) {                                  \
                const int idx = tid + 512 * i;                             \
                const int r2 = idx >> 3, c2 = idx & 7;                     \
                cp_async16(GBUF(b) + t * GK_TILE_BYTES + r2 * 128 +        \
                               (((unsigned)c2 ^ (unsigned)(r2 & 7)) << 4), \
                           srcp + (size_t)(m0 + r2) * 128 + (s) * 8 + c2); \
            } } } } while (0)

#define GK_CPB(s, b)                                                       \
    do {                                                                   \
        _Pragma("unroll")                                                  \
        for (int t = 0; t < 2; t++) {                                      \
            const uint4* srcp = t ? Wl4 : Wh4;                             \
            _Pragma("unroll")                                              \
            for (int i = 0; i < 2; i++) {                                  \
                const int idx = tid + 512 * i;                             \
                const int r2 = idx >> 3, c2 = idx & 7;                     \
                cp_async16(GBUF(b) + (2 + t) * GK_TILE_BYTES + r2 * 128 +  \
                               (((unsigned)c2 ^ (unsigned)(r2 & 7)) << 4), \
                           srcp + (size_t)(n0 + r2) * 128 + (s) * 8 + c2); \
            } } } while (0)

    // prologue: stage 0 fully staged into buf0, LDG for stage 1 in regs
    GK_LDGA(0);
    GK_CPA(0, 0);
    GK_CPB(0, 0);
    cp_commit();
    GK_STSA(0);
    GK_LDGA(1);

    for (int s = 0; s < GK_STAGES; s++) {
        const int cur = s & 1;
        if (s + 1 < GK_STAGES) {
            GK_CPA(s + 1, cur ^ 1);
            GK_CPB(s + 1, cur ^ 1);
            cp_commit();
            GK_STSA(cur ^ 1);
            if (s + 2 < GK_STAGES) GK_LDGA(s + 2);
            cp_wait1();
        } else {
            cp_wait0();
        }
        __syncthreads();

        // ---- MMA from buf cur ----
        const unsigned bo = sbase + (unsigned)cur * GK_BUF_BYTES;
        const unsigned sAh = bo;
        const unsigned sAl = bo + GK_TILE_BYTES;
        const unsigned sBh = bo + 2 * GK_TILE_BYTES;
        const unsigned sBl = bo + 3 * GK_TILE_BYTES;
#pragma unroll
        for (int ks = 0; ks < 4; ks++) {
            unsigned bh[2][4], bl[2][4];
#pragma unroll
            for (int j2 = 0; j2 < 2; j2++) {
                const unsigned roff =
                    (unsigned)(wn + 16 * j2 + brow) * 128 +
                    ((((unsigned)(2 * ks) + bhi) << 4) ^ bxor);
                ldmx4(bh[j2], sBh + roff);
                ldmx4(bl[j2], sBl + roff);
            }
#pragma unroll
            for (int i = 0; i < 2; i++) {
                const unsigned aoff =
                    (unsigned)(wm + 16 * i + arow) * 128 +
                    ((((unsigned)(2 * ks) + ahi) << 4) ^ axor);
                unsigned ah[4], al[4];
                ldmx4(ah, sAh + aoff);
                ldmx4(al, sAl + aoff);
#pragma unroll
                for (int j = 0; j < 4; j++) {
                    const unsigned b0h = bh[j >> 1][(j & 1) * 2];
                    const unsigned b1h = bh[j >> 1][(j & 1) * 2 + 1];
                    const unsigned b0l = bl[j >> 1][(j & 1) * 2];
                    const unsigned b1l = bl[j >> 1][(j & 1) * 2 + 1];
                    mma_bf16(d[i][j], ah, b0h, b1h);
                    mma_bf16(d[i][j], ah, b0l, b1l);
                    mma_bf16(d[i][j], al, b0h, b1h);
                }
            }
        }
        __syncthreads();
    }
#undef GK_LDGA
#undef GK_STSA
#undef GK_CPA
#undef GK_CPB
#undef GBUF

    // ---- epilogue ----
    const int r0 = m0 + wm + (lane >> 2);
    const int cb = n0 + wn + 2 * (lane & 3);
    if (SC) {
#pragma unroll
        for (int i = 0; i < 2; i++)
#pragma unroll
            for (int j = 0; j < 4; j++) {
                unsigned h0, l0, h1, l1;
                cvt_split2(d[i][j][0], d[i][j][1], h0, l0);
                cvt_split2(d[i][j][2], d[i][j][3], h1, l1);
                const size_t idx =
                    (size_t)(r0 + 16 * i) * DM2 + (cb >> 1) + 4 * j;
                Ch[idx] = h0;
                Cl[idx] = l0;
                Ch[idx + 8 * DM2] = h1;
                Cl[idx + 8 * DM2] = l1;
            }
    } else {
        float* Cbase = C + (size_t)r0 * DMODEL + cb;
#pragma unroll
        for (int i = 0; i < 2; i++)
#pragma unroll
            for (int j = 0; j < 4; j++) {
                *(float2*)(Cbase + (size_t)(16 * i) * DMODEL + 8 * j) =
                    make_float2(d[i][j][0], d[i][j][1]);
                *(float2*)(Cbase + (size_t)(16 * i + 8) * DMODEL + 8 * j) =
                    make_float2(d[i][j][2], d[i][j][3]);
            }
    }
}

__global__ void __launch_bounds__(512, 1)
mha_gemm_qkv(const float* __restrict__ q, const float* __restrict__ k,
             const float* __restrict__ v) {
    const int z = blockIdx.z;
    const float* A = (z == 0) ? q : (z == 1) ? k : v;
    const uint4* Wh4 = (const uint4*)g_Wh + (size_t)z * WU4;
    const uint4* Wl4 = (const uint4*)g_Wl + (size_t)z * WU4;
    unsigned* Ch = (z == 0) ? g_Qh : (z == 1) ? g_Kh : g_Vh;
    unsigned* Cl = (z == 0) ? g_Ql : (z == 1) ? g_Kl : g_Vl;
    gemm_body<false, true>(A, nullptr, nullptr, Wh4, Wl4, nullptr, Ch, Cl);
}

__global__ void __launch_bounds__(512, 1)
mha_gemm_out(float* __restrict__ out) {
    const uint4* Wh4 = (const uint4*)g_Wh + (size_t)3 * WU4;
    const uint4* Wl4 = (const uint4*)g_Wl + (size_t)3 * WU4;
    gemm_body<true, false>(nullptr, (const uint4*)g_Xh, (const uint4*)g_Xl,
                           Wh4, Wl4, out, nullptr, nullptr);
}

// ---------------------------------------------------------------------------
// Tensor-core flash attention (verified R12, unchanged).
// ---------------------------------------------------------------------------
#define ATT_BM 128
#define ATT_BN 64
#define ATT_TILE_B (ATT_BN * 128)            // 8 KB per tensor-half tile
#define ATT_BUF_B (4 * ATT_TILE_B)           // Kh,Kl,Vh,Vl = 32 KB
#define ATT_SMEM (2 * ATT_BUF_B + 1024)

__global__ void __launch_bounds__(256, 1)
mha_flash_attn_tc(const int* __restrict__ mask) {
    extern __shared__ char att_raw[];
    char* base = (char*)(((unsigned long long)(size_t)att_raw + 1023ull) &
                         ~1023ull);
    const unsigned sbase = smem_u32(base);

    const int tid = threadIdx.x;
    const int wid = tid >> 5;
    const int lane = tid & 31;
    const int q0 = blockIdx.x * ATT_BM;
    const int bh = blockIdx.y;
    const int b = bh >> 4;
    const int h = bh & 15;

    // ---- prologue: Q -> buf1 (copy), K/V tile 0 -> buf0 ----
#pragma unroll
    for (int i = 0; i < 8; i++) {
        const int idx = tid + 256 * i;
        const int t = i >> 1;
        const int idx2 = (idx & 511);
        const int r = idx2 >> 3, cc = idx2 & 7;
        const unsigned* src =
            (t == 0) ? g_Kh : (t == 1) ? g_Kl : (t == 2) ? g_Vh : g_Vl;
        const size_t gi = (size_t)(b * SEQ + r) * DM2 + h * 32 + cc * 4;
        char* dst = base + t * ATT_TILE_B + r * 128 + (((cc ^ (r & 7))) << 4);
        cp_async16(dst, src + gi);
    }
#pragma unroll
    for (int i = 0; i < 8; i++) {
        const int idx = tid + 256 * i;
        const int half = i >> 2;
        const int idx2 = idx & 1023;
        const int r = idx2 >> 3, cc = idx2 & 7;
        const unsigned* src = half ? g_Ql : g_Qh;
        const size_t gi = (size_t)(b * SEQ + q0 + r) * DM2 + h * 32 + cc * 4;
        char* dst = base + ATT_BUF_B + half * (2 * ATT_TILE_B) +
                    r * 128 + (((cc ^ (r & 7))) << 4);
        cp_async16(dst, src + gi);
    }
    cp_commit();
    cp_wait0();
    __syncthreads();

    // ---- Q fragments (registers, whole kernel) ----
    unsigned qh[4][4], ql[4][4];
    {
        const int arow = lane & 15;
        const unsigned ahi = (unsigned)(lane >> 4);
        const int row = 16 * wid + arow;
#pragma unroll
        for (int kk = 0; kk < 4; kk++) {
            const unsigned ch = 2 * (unsigned)kk + ahi;
            const unsigned off =
                (unsigned)(row * 128) + ((ch ^ (unsigned)(row & 7)) << 4);
            ldmx4(qh[kk], sbase + ATT_BUF_B + off);
            ldmx4(ql[kk], sbase + ATT_BUF_B + 2 * ATT_TILE_B + off);
        }
    }
    __syncthreads();

    float o[8][4];
#pragma unroll
    for (int j = 0; j < 8; j++)
#pragma unroll
        for (int e = 0; e < 4; e++) o[j][e] = 0.0f;
    float m0 = -1e30f, m1 = -1e30f, l0 = 0.0f, l1 = 0.0f;

    const int grow = q0 + 16 * wid + (lane >> 2);
    const int* mrow0 = mask + ((size_t)b * SEQ + grow) * SEQ;
    const int* mrow1 = mrow0 + 8 * SEQ;

    const int brow = (lane & 7) + ((lane >> 4) << 3);
    const unsigned bxor = (unsigned)((brow & 7) << 4);
    const unsigned bhi = (unsigned)((lane >> 3) & 1);
    const int vtt = lane >> 3;
    const int vrow_lo = ((vtt & 1) << 3) + (lane & 7);
    const unsigned vch_add = (unsigned)(vtt >> 1);

    for (int n = 0; n < SEQ / ATT_BN; n++) {
        const int j0 = n * ATT_BN;
        const int cur = n & 1;
        if (n > 0) {
            cp_wait0();
            __syncthreads();
        }
        if (n + 1 < SEQ / ATT_BN) {
            char* bufn = base + (cur ^ 1) * ATT_BUF_B;
            const int jn = j0 + ATT_BN;
#pragma unroll
            for (int i = 0; i < 8; i++) {
                const int idx = tid + 256 * i;
                const int t = i >> 1;
                const int idx2 = (idx & 511);
                const int r = idx2 >> 3, cc = idx2 & 7;
                const unsigned* src =
                    (t == 0) ? g_Kh : (t == 1) ? g_Kl : (t == 2) ? g_Vh : g_Vl;
                const size_t gi =
                    (size_t)(b * SEQ + jn + r) * DM2 + h * 32 + cc * 4;
                char* dst =
                    bufn + t * ATT_TILE_B + r * 128 + (((cc ^ (r & 7))) << 4);
                cp_async16(dst, src + gi);
            }
            cp_commit();
        }

        const unsigned bo = sbase + (unsigned)cur * ATT_BUF_B;
        const unsigned sKh = bo;
        const unsigned sKl = bo + ATT_TILE_B;
        const unsigned sVh = bo + 2 * ATT_TILE_B;
        const unsigned sVl = bo + 3 * ATT_TILE_B;

        // ---- S = Q.K^T (3-way split) ----
        float c[8][4];
#pragma unroll
        for (int j = 0; j < 8; j++)
#pragma unroll
            for (int e = 0; e < 4; e++) c[j][e] = 0.0f;

#pragma unroll
        for (int ks = 0; ks < 4; ks++) {
#pragma unroll
            for (int j2 = 0; j2 < 4; j2++) {
                const int kr = 16 * j2 + brow;
                const unsigned off = (unsigned)(kr * 128) +
                    ((((unsigned)(2 * ks) + bhi) << 4) ^ bxor);
                unsigned kbh[4], kbl[4];
                ldmx4(kbh, sKh + off);
                ldmx4(kbl, sKl + off);
#pragma unroll
                for (int jj = 0; jj < 2; jj++) {
                    const int j = 2 * j2 + jj;
                    mma_bf16(c[j], qh[ks], kbh[2 * jj], kbh[2 * jj + 1]);
                    mma_bf16(c[j], qh[ks], kbl[2 * jj], kbl[2 * jj + 1]);
                    mma_bf16(c[j], ql[ks], kbh[2 * jj], kbh[2 * jj + 1]);
                }
            }
        }

        // ---- scale + mask ----
        const int mcol = j0 + 2 * (lane & 3);
#pragma unroll
        for (int j = 0; j < 8; j++) {
            const int2 mv0 = *(const int2*)(mrow0 + mcol + 8 * j);
            const int2 mv1 = *(const int2*)(mrow1 + mcol + 8 * j);
            c[j][0] = mv0.x ? c[j][0] * 0.125f : -1e9f;
            c[j][1] = mv0.y ? c[j][1] * 0.125f : -1e9f;
            c[j][2] = mv1.x ? c[j][2] * 0.125f : -1e9f;
            c[j][3] = mv1.y ? c[j][3] * 0.125f : -1e9f;
        }

        // ---- row max (quad shuffle reduce) ----
        float t0 = -1e30f, t1 = -1e30f;
#pragma unroll
        for (int j = 0; j < 8; j++) {
            t0 = fmaxf(t0, fmaxf(c[j][0], c[j][1]));
            t1 = fmaxf(t1, fmaxf(c[j][2], c[j][3]));
        }
        t0 = fmaxf(t0, __shfl_xor_sync(0xffffffffu, t0, 1));
        t0 = fmaxf(t0, __shfl_xor_sync(0xffffffffu, t0, 2));
        t1 = fmaxf(t1, __shfl_xor_sync(0xffffffffu, t1, 1));
        t1 = fmaxf(t1, __shfl_xor_sync(0xffffffffu, t1, 2));

        const float mn0 = fmaxf(m0, t0);
        const float mn1 = fmaxf(m1, t1);
        const float al0 = __expf(m0 - mn0);
        const float al1 = __expf(m1 - mn1);
        m0 = mn0; m1 = mn1;
        l0 *= al0; l1 *= al1;
#pragma unroll
        for (int j = 0; j < 8; j++) {
            o[j][0] *= al0; o[j][1] *= al0;
            o[j][2] *= al1; o[j][3] *= al1;
        }

        // ---- exponentiate, accumulate row sums ----
#pragma unroll
        for (int j = 0; j < 8; j++) {
            c[j][0] = __expf(c[j][0] - m0);
            c[j][1] = __expf(c[j][1] - m0);
            c[j][2] = __expf(c[j][2] - m1);
            c[j][3] = __expf(c[j][3] - m1);
            l0 += c[j][0] + c[j][1];
            l1 += c[j][2] + c[j][3];
        }

        // ---- O += P.V (register repack, 3-way split) ----
#pragma unroll
        for (int kk = 0; kk < 4; kk++) {
            unsigned pah[4], pal[4];
            cvt_split2(c[2 * kk][0],     c[2 * kk][1],     pah[0], pal[0]);
            cvt_split2(c[2 * kk][2],     c[2 * kk][3],     pah[1], pal[1]);
            cvt_split2(c[2 * kk + 1][0], c[2 * kk + 1][1], pah[2], pal[2]);
            cvt_split2(c[2 * kk + 1][2], c[2 * kk + 1][3], pah[3], pal[3]);
#pragma unroll
            for (int j2 = 0; j2 < 4; j2++) {
                const int vr = 16 * kk + vrow_lo;
                const unsigned ch = 2 * (unsigned)j2 + vch_add;
                const unsigned off = (unsigned)(vr * 128) +
                    ((ch ^ (unsigned)(vr & 7)) << 4);
                unsigned vbh[4], vbl[4];
                ldmx4t(vbh, sVh + off);
                ldmx4t(vbl, sVl + off);
#pragma unroll
                for (int jj = 0; jj < 2; jj++) {
                    const int j = 2 * j2 + jj;
                    mma_bf16(o[j], pah, vbh[2 * jj], vbh[2 * jj + 1]);
                    mma_bf16(o[j], pah, vbl[2 * jj], vbl[2 * jj + 1]);
                    mma_bf16(o[j], pal, vbh[2 * jj], vbh[2 * jj + 1]);
                }
            }
        }
    }

    // ---- finalize ----
    l0 += __shfl_xor_sync(0xffffffffu, l0, 1);
    l0 += __shfl_xor_sync(0xffffffffu, l0, 2);
    l1 += __shfl_xor_sync(0xffffffffu, l1, 1);
    l1 += __shfl_xor_sync(0xffffffffu, l1, 2);
    const float inv0 = 1.0f / l0;
    const float inv1 = 1.0f / l1;

    const size_t xrow = (size_t)(b * SEQ + grow) * DM2 + h * 32 + (lane & 3);
#pragma unroll
    for (int j = 0; j < 8; j++) {
        unsigned h0, lo0, h1, lo1;
        cvt_split2(o[j][0] * inv0, o[j][1] * inv0, h0, lo0);
        cvt_split2(o[j][2] * inv1, o[j][3] * inv1, h1, lo1);
        g_Xh[xrow + 4 * j] = h0;
        g_Xl[xrow + 4 * j] = lo0;
        g_Xh[xrow + 8 * DM2 + 4 * j] = h1;
        g_Xl[xrow + 8 * DM2 + 4 * j] = lo1;
    }
}

// ---------------------------------------------------------------------------
// Launch
// Inputs (metadata order): q, k, v, w_q, w_k, w_v, w_o, mask
// ---------------------------------------------------------------------------
extern "C" void kernel_launch(void* const* d_in, const int* in_sizes, int n_in,
                              void* d_out, int out_size) {
    const float* q  = (const float*)d_in[0];
    const float* k  = (const float*)d_in[1];
    const float* v  = (const float*)d_in[2];
    const float* wq = (const float*)d_in[3];
    const float* wk = (const float*)d_in[4];
    const float* wv = (const float*)d_in[5];
    const float* wo = (const float*)d_in[6];
    const int* mask = (const int*)d_in[7];
    float* out = (float*)d_out;

    cudaFuncSetAttribute(mha_gemm_qkv,
                         cudaFuncAttributeMaxDynamicSharedMemorySize, GEMM_SMEM);
    cudaFuncSetAttribute(mha_gemm_out,
                         cudaFuncAttributeMaxDynamicSharedMemorySize, GEMM_SMEM);
    cudaFuncSetAttribute(mha_flash_attn_tc,
                         cudaFuncAttributeMaxDynamicSharedMemorySize, ATT_SMEM);

    // 0) pre-split all four weight matrices to bf16 hi/lo
    dim3 gw(512, 4);
    presplit_w<<<gw, 256>>>(wq, wk, wv, wo);

    // 1) Q/K/V projections: grid (N/128, M/128, 3)
    dim3 gqkv(DMODEL / 128, MROWS / 128, 3);
    mha_gemm_qkv<<<gqkv, 512, GEMM_SMEM>>>(q, k, v);

    // 2) attention: grid (S/128, B*H)
    dim3 gatt(SEQ / ATT_BM, BATCH * NHEAD);
    mha_flash_attn_tc<<<gatt, 256, ATT_SMEM>>>(mask);

    // 3) output projection
    dim3 gout(DMODEL / 128, MROWS / 128, 1);
    mha_gemm_out<<<gout, 512, GEMM_SMEM>>>(out);
}

// round 14
// speedup vs baseline: 1.3737x; 1.3737x over previous
#include <cuda_runtime.h>
#include <cuda_bf16.h>

// Problem constants
#define BATCH   2
#define SEQ     2048
#define DMODEL  1024
#define NHEAD   16
#define DK      64
#define MROWS   (BATCH * SEQ)       // 4096
#define DM2     (DMODEL / 2)        // u32 (16-bit pair) per row
#define WU4     (DMODEL * DMODEL / 8)  // uint4 per weight matrix (131072)

// ---------------------------------------------------------------------------
// Scratch: Q/K/V as fp16 (u32 = f16x2); X and W as bf16 hi/lo split
// ---------------------------------------------------------------------------
__device__ unsigned g_Qf[MROWS * DM2];
__device__ unsigned g_Kf[MROWS * DM2];
__device__ unsigned g_Vf[MROWS * DM2];
__device__ unsigned g_Xh[MROWS * DM2], g_Xl[MROWS * DM2];
__device__ unsigned g_Wh[4 * DMODEL * DM2], g_Wl[4 * DMODEL * DM2];

// ---------------------------------------------------------------------------
// Warp-level tensor core helpers (sm_80-baseline PTX: works on plain sm_103)
// ---------------------------------------------------------------------------
__device__ __forceinline__ unsigned smem_u32(const void* p) {
    return (unsigned)__cvta_generic_to_shared(p);
}
__device__ __forceinline__ void ldmx4(unsigned* r, unsigned addr) {
    asm volatile(
        "ldmatrix.sync.aligned.m8n8.x4.shared.b16 {%0,%1,%2,%3}, [%4];"
        : "=r"(r[0]), "=r"(r[1]), "=r"(r[2]), "=r"(r[3]) : "r"(addr));
}
__device__ __forceinline__ void ldmx4t(unsigned* r, unsigned addr) {
    asm volatile(
        "ldmatrix.sync.aligned.m8n8.x4.trans.shared.b16 {%0,%1,%2,%3}, [%4];"
        : "=r"(r[0]), "=r"(r[1]), "=r"(r[2]), "=r"(r[3]) : "r"(addr));
}
__device__ __forceinline__ void mma_bf16(float* d, const unsigned* a,
                                         unsigned b0, unsigned b1) {
    asm volatile(
        "mma.sync.aligned.m16n8k16.row.col.f32.bf16.bf16.f32 "
        "{%0,%1,%2,%3}, {%4,%5,%6,%7}, {%8,%9}, {%0,%1,%2,%3};"
        : "+f"(d[0]), "+f"(d[1]), "+f"(d[2]), "+f"(d[3])
        : "r"(a[0]), "r"(a[1]), "r"(a[2]), "r"(a[3]), "r"(b0), "r"(b1));
}
__device__ __forceinline__ void mma_f16(float* d, const unsigned* a,
                                        unsigned b0, unsigned b1) {
    asm volatile(
        "mma.sync.aligned.m16n8k16.row.col.f32.f16.f16.f32 "
        "{%0,%1,%2,%3}, {%4,%5,%6,%7}, {%8,%9}, {%0,%1,%2,%3};"
        : "+f"(d[0]), "+f"(d[1]), "+f"(d[2]), "+f"(d[3])
        : "r"(a[0]), "r"(a[1]), "r"(a[2]), "r"(a[3]), "r"(b0), "r"(b1));
}

// fp32 pair -> bf16x2 hi + bf16x2 lo
__device__ __forceinline__ void cvt_split2(float x0, float x1,
                                           unsigned& h, unsigned& l) {
    asm("cvt.rn.satfinite.bf16x2.f32 %0, %1, %2;" : "=r"(h) : "f"(x1), "f"(x0));
    float hf0 = __uint_as_float(h << 16);
    float hf1 = __uint_as_float(h & 0xffff0000u);
    float l0 = x0 - hf0;
    float l1 = x1 - hf1;
    asm("cvt.rn.satfinite.bf16x2.f32 %0, %1, %2;" : "=r"(l) : "f"(l1), "f"(l0));
}
// fp32 pair -> fp16x2 (lo half = x0)
__device__ __forceinline__ unsigned pack_f16(float x0, float x1) {
    unsigned r;
    asm("cvt.rn.f16x2.f32 %0, %1, %2;" : "=r"(r) : "f"(x1), "f"(x0));
    return r;
}
__device__ __forceinline__ void split_store(float4 a, float4 b,
                                            char* dst_hi, char* dst_lo) {
    uint4 h, l;
    cvt_split2(a.x, a.y, h.x, l.x);
    cvt_split2(a.z, a.w, h.y, l.y);
    cvt_split2(b.x, b.y, h.z, l.z);
    cvt_split2(b.z, b.w, h.w, l.w);
    *(uint4*)dst_hi = h;
    *(uint4*)dst_lo = l;
}

// cp.async 16B (bypass-L1)
__device__ __forceinline__ void cp_async16(void* smem_ptr, const void* gptr) {
    unsigned saddr = (unsigned)__cvta_generic_to_shared(smem_ptr);
    asm volatile("cp.async.cg.shared.global [%0], [%1], 16;"
                 :: "r"(saddr), "l"(gptr) : "memory");
}
__device__ __forceinline__ void cp_commit() {
    asm volatile("cp.async.commit_group;" ::: "memory");
}
__device__ __forceinline__ void cp_wait0() {
    asm volatile("cp.async.wait_group 0;" ::: "memory");
}
__device__ __forceinline__ void cp_wait1() {
    asm volatile("cp.async.wait_group 1;" ::: "memory");
}

// ---------------------------------------------------------------------------
// Weight pre-split: w[1024x1024] fp32 -> hi/lo bf16x2
// ---------------------------------------------------------------------------
__global__ void __launch_bounds__(256)
presplit_w(const float* __restrict__ w0, const float* __restrict__ w1,
           const float* __restrict__ w2, const float* __restrict__ w3) {
    const int m = blockIdx.y;
    const float* src = (m == 0) ? w0 : (m == 1) ? w1 : (m == 2) ? w2 : w3;
    const int gid = blockIdx.x * 256 + threadIdx.x;   // 0..131071
    const float4* s4 = (const float4*)src;
    float4 a = s4[2 * gid], b = s4[2 * gid + 1];
    uint4 h, l;
    cvt_split2(a.x, a.y, h.x, l.x);
    cvt_split2(a.z, a.w, h.y, l.y);
    cvt_split2(b.x, b.y, h.z, l.z);
    cvt_split2(b.z, b.w, h.w, l.w);
    ((uint4*)g_Wh)[(size_t)m * WU4 + gid] = h;
    ((uint4*)g_Wl)[(size_t)m * WU4 + gid] = l;
}

// ---------------------------------------------------------------------------
// Tensor-core NT GEMM (3-way bf16 split): C[m,n] = sum_k A[m,k]*W[n,k].
// CTA 128x128, 512 threads, 16 warps (4x4, warp tile 32x32), cp.async
// double-buffered. PA: A pre-split bf16 hi/lo (copy); else fp32 in-loop split.
// F16OUT: C written as fp16 (u32 pairs) to Cf; else fp32 to C.
// ---------------------------------------------------------------------------
#define GK_STAGES 16
#define GK_TILE_BYTES (128 * 64 * 2)            // 16 KB per tensor-half
#define GK_BUF_BYTES (4 * GK_TILE_BYTES)        // Ah, Al, Bh, Bl = 64 KB
#define GEMM_SMEM (2 * GK_BUF_BYTES + 1024)

template <bool PA, bool F16OUT>
__device__ __forceinline__ void gemm_body(
    const float* __restrict__ A,
    const uint4* __restrict__ Ah4, const uint4* __restrict__ Al4,
    const uint4* __restrict__ Wh4, const uint4* __restrict__ Wl4,
    float* __restrict__ C, unsigned* __restrict__ Cf) {
    extern __shared__ char dyn_raw[];
    char* dynb = (char*)(((unsigned long long)(size_t)dyn_raw + 1023ull) &
                         ~1023ull);
    const unsigned sbase = smem_u32(dynb);

    const int tid = threadIdx.x;
    const int wid = tid >> 5;
    const int lane = tid & 31;
    const int m0 = blockIdx.y * 128;
    const int n0 = blockIdx.x * 128;

    const float4* A4 = (const float4*)A;

    const int rb = tid >> 3;      // 0..63
    const int cc = tid & 7;

    const int wm = (wid >> 2) * 32;
    const int wn = (wid & 3) * 32;
    const int arow = lane & 15;
    const unsigned ahi = (unsigned)(lane >> 4);
    const unsigned axor = (unsigned)((arow & 7) << 4);
    const int brow = (lane & 7) + ((lane >> 4) << 3);
    const unsigned bxor = (unsigned)((brow & 7) << 4);
    const unsigned bhi = (unsigned)((lane >> 3) & 1);

    float d[2][4][4];
#pragma unroll
    for (int i = 0; i < 2; i++)
#pragma unroll
        for (int j = 0; j < 4; j++)
#pragma unroll
            for (int e = 0; e < 4; e++) d[i][j][e] = 0.0f;

    float4 ra[2][2];

#define GBUF(b) (dynb + (b) * GK_BUF_BYTES)

#define GK_LDGA(s)                                                         \
    do { if (!PA) {                                                        \
        _Pragma("unroll")                                                  \
        for (int i = 0; i < 2; i++) {                                      \
            const size_t ga =                                              \
                (size_t)(m0 + rb + 64 * i) * 256 + (s) * 16 + cc * 2;      \
            ra[i][0] = A4[ga];                                             \
            ra[i][1] = A4[ga + 1];                                         \
        } } } while (0)

#define GK_STSA(b)                                                         \
    do { if (!PA) {                                                        \
        char* Ahp = GBUF(b);                                               \
        char* Alp = Ahp + GK_TILE_BYTES;                                   \
        _Pragma("unroll")                                                  \
        for (int i = 0; i < 2; i++) {                                      \
            const int r = rb + 64 * i;                                     \
            const unsigned sw = (unsigned)(r * 128) +                      \
                (((unsigned)cc ^ (unsigned)(r & 7)) << 4);                 \
            split_store(ra[i][0], ra[i][1], Ahp + sw, Alp + sw);           \
        } } } while (0)

#define GK_CPA(s, b)                                                       \
    do { if (PA) {                                                         \
        _Pragma("unroll")                                                  \
        for (int t = 0; t < 2; t++) {                                      \
            const uint4* srcp = t ? Al4 : Ah4;                             \
            _Pragma("unroll")                                              \
            for (int i = 0; i < 2; i++) {                                  \
                const int idx = tid + 512 * i;                             \
                const int r2 = idx >> 3, c2 = idx & 7;                     \
                cp_async16(GBUF(b) + t * GK_TILE_BYTES + r2 * 128 +        \
                               (((unsigned)c2 ^ (unsigned)(r2 & 7)) << 4), \
                           srcp + (size_t)(m0 + r2) * 128 + (s) * 8 + c2); \
            } } } } while (0)

#define GK_CPB(s, b)                                                       \
    do {                                                                   \
        _Pragma("unroll")                                                  \
        for (int t = 0; t < 2; t++) {                                      \
            const uint4* srcp = t ? Wl4 : Wh4;                             \
            _Pragma("unroll")                                              \
            for (int i = 0; i < 2; i++) {                                  \
                const int idx = tid + 512 * i;                             \
                const int r2 = idx >> 3, c2 = idx & 7;                     \
                cp_async16(GBUF(b) + (2 + t) * GK_TILE_BYTES + r2 * 128 +  \
                               (((unsigned)c2 ^ (unsigned)(r2 & 7)) << 4), \
                           srcp + (size_t)(n0 + r2) * 128 + (s) * 8 + c2); \
            } } } while (0)

    GK_LDGA(0);
    GK_CPA(0, 0);
    GK_CPB(0, 0);
    cp_commit();
    GK_STSA(0);
    GK_LDGA(1);

    for (int s = 0; s < GK_STAGES; s++) {
        const int cur = s & 1;
        if (s + 1 < GK_STAGES) {
            GK_CPA(s + 1, cur ^ 1);
            GK_CPB(s + 1, cur ^ 1);
            cp_commit();
            GK_STSA(cur ^ 1);
            if (s + 2 < GK_STAGES) GK_LDGA(s + 2);
            cp_wait1();
        } else {
            cp_wait0();
        }
        __syncthreads();

        const unsigned bo = sbase + (unsigned)cur * GK_BUF_BYTES;
        const unsigned sAh = bo;
        const unsigned sAl = bo + GK_TILE_BYTES;
        const unsigned sBh = bo + 2 * GK_TILE_BYTES;
        const unsigned sBl = bo + 3 * GK_TILE_BYTES;
#pragma unroll
        for (int ks = 0; ks < 4; ks++) {
            unsigned bh[2][4], bl[2][4];
#pragma unroll
            for (int j2 = 0; j2 < 2; j2++) {
                const unsigned roff =
                    (unsigned)(wn + 16 * j2 + brow) * 128 +
                    ((((unsigned)(2 * ks) + bhi) << 4) ^ bxor);
                ldmx4(bh[j2], sBh + roff);
                ldmx4(bl[j2], sBl + roff);
            }
#pragma unroll
            for (int i = 0; i < 2; i++) {
                const unsigned aoff =
                    (unsigned)(wm + 16 * i + arow) * 128 +
                    ((((unsigned)(2 * ks) + ahi) << 4) ^ axor);
                unsigned ah[4], al[4];
                ldmx4(ah, sAh + aoff);
                ldmx4(al, sAl + aoff);
#pragma unroll
                for (int j = 0; j < 4; j++) {
                    const unsigned b0h = bh[j >> 1][(j & 1) * 2];
                    const unsigned b1h = bh[j >> 1][(j & 1) * 2 + 1];
                    const unsigned b0l = bl[j >> 1][(j & 1) * 2];
                    const unsigned b1l = bl[j >> 1][(j & 1) * 2 + 1];
                    mma_bf16(d[i][j], ah, b0h, b1h);
                    mma_bf16(d[i][j], ah, b0l, b1l);
                    mma_bf16(d[i][j], al, b0h, b1h);
                }
            }
        }
        __syncthreads();
    }
#undef GK_LDGA
#undef GK_STSA
#undef GK_CPA
#undef GK_CPB
#undef GBUF

    // ---- epilogue ----
    const int r0 = m0 + wm + (lane >> 2);
    const int cb = n0 + wn + 2 * (lane & 3);
    if (F16OUT) {
#pragma unroll
        for (int i = 0; i < 2; i++)
#pragma unroll
            for (int j = 0; j < 4; j++) {
                const unsigned p0 = pack_f16(d[i][j][0], d[i][j][1]);
                const unsigned p1 = pack_f16(d[i][j][2], d[i][j][3]);
                const size_t idx =
                    (size_t)(r0 + 16 * i) * DM2 + (cb >> 1) + 4 * j;
                Cf[idx] = p0;
                Cf[idx + 8 * DM2] = p1;
            }
    } else {
        float* Cbase = C + (size_t)r0 * DMODEL + cb;
#pragma unroll
        for (int i = 0; i < 2; i++)
#pragma unroll
            for (int j = 0; j < 4; j++) {
                *(float2*)(Cbase + (size_t)(16 * i) * DMODEL + 8 * j) =
                    make_float2(d[i][j][0], d[i][j][1]);
                *(float2*)(Cbase + (size_t)(16 * i + 8) * DMODEL + 8 * j) =
                    make_float2(d[i][j][2], d[i][j][3]);
            }
    }
}

__global__ void __launch_bounds__(512, 1)
mha_gemm_qkv(const float* __restrict__ q, const float* __restrict__ k,
             const float* __restrict__ v) {
    const int z = blockIdx.z;
    const float* A = (z == 0) ? q : (z == 1) ? k : v;
    const uint4* Wh4 = (const uint4*)g_Wh + (size_t)z * WU4;
    const uint4* Wl4 = (const uint4*)g_Wl + (size_t)z * WU4;
    unsigned* Cf = (z == 0) ? g_Qf : (z == 1) ? g_Kf : g_Vf;
    gemm_body<false, true>(A, nullptr, nullptr, Wh4, Wl4, nullptr, Cf);
}

__global__ void __launch_bounds__(512, 1)
mha_gemm_out(float* __restrict__ out) {
    const uint4* Wh4 = (const uint4*)g_Wh + (size_t)3 * WU4;
    const uint4* Wl4 = (const uint4*)g_Wl + (size_t)3 * WU4;
    gemm_body<true, false>(nullptr, (const uint4*)g_Xh, (const uint4*)g_Xl,
                           Wh4, Wl4, out, nullptr);
}

// ---------------------------------------------------------------------------
// fp16 single-pass tensor-core flash attention.
// CTA = 128 q-rows x one (batch, head); 256 threads = 8 warps x 16 rows.
// Q/K/V are fp16 (written by the projection GEMM). One MMA per logical
// fragment op (no hi/lo split). K/V tiles double-buffered via cp.async.
// Output X written as bf16 hi/lo for the 3-way out-projection.
// ---------------------------------------------------------------------------
#define ATT_BM 128
#define ATT_BN 64
#define ATT_TILE_B (ATT_BN * 128)            // 8 KB: 64 rows x 128B fp16
#define ATT_BUF_B (2 * ATT_TILE_B)           // Kf + Vf = 16 KB per buffer
#define ATT_SMEM (2 * ATT_BUF_B + 1024)      // ~33 KB

__global__ void __launch_bounds__(256)
mha_flash_attn_tc(const int* __restrict__ mask) {
    extern __shared__ char att_raw[];
    char* base = (char*)(((unsigned long long)(size_t)att_raw + 1023ull) &
                         ~1023ull);
    const unsigned sbase = smem_u32(base);

    const int tid = threadIdx.x;
    const int wid = tid >> 5;
    const int lane = tid & 31;
    const int q0 = blockIdx.x * ATT_BM;
    const int bh = blockIdx.y;
    const int b = bh >> 4;
    const int h = bh & 15;

    // ---- prologue: K/V tile 0 -> buf0; Q (16 KB) -> buf1 region ----
#pragma unroll
    for (int i = 0; i < 4; i++) {               // K/V tile 0: 1024 chunks
        const int idx = tid + 256 * i;
        const int t = idx >> 9;                 // 0: K, 1: V
        const int idx2 = idx & 511;
        const int r = idx2 >> 3, cc = idx2 & 7;
        const unsigned* src = t ? g_Vf : g_Kf;
        const size_t gi = (size_t)(b * SEQ + r) * DM2 + h * 32 + cc * 4;
        char* dst = base + t * ATT_TILE_B + r * 128 + ((cc ^ (r & 7)) << 4);
        cp_async16(dst, src + gi);
    }
#pragma unroll
    for (int i = 0; i < 4; i++) {               // Q: 1024 chunks -> buf1
        const int idx = tid + 256 * i;
        const int r = idx >> 3, cc = idx & 7;
        const size_t gi = (size_t)(b * SEQ + q0 + r) * DM2 + h * 32 + cc * 4;
        char* dst = base + ATT_BUF_B + r * 128 + ((cc ^ (r & 7)) << 4);
        cp_async16(dst, g_Qf + gi);
    }
    cp_commit();
    cp_wait0();
    __syncthreads();

    // ---- Q fragments (registers, whole kernel) ----
    unsigned qf[4][4];
    {
        const int arow = lane & 15;
        const unsigned ahi = (unsigned)(lane >> 4);
        const int row = 16 * wid + arow;
#pragma unroll
        for (int kk = 0; kk < 4; kk++) {
            const unsigned ch = 2 * (unsigned)kk + ahi;
            const unsigned off =
                (unsigned)(row * 128) + ((ch ^ (unsigned)(row & 7)) << 4);
            ldmx4(qf[kk], sbase + ATT_BUF_B + off);
        }
    }
    __syncthreads();   // Q read; buf1 reusable for K/V prefetch

    float o[8][4];
#pragma unroll
    for (int j = 0; j < 8; j++)
#pragma unroll
        for (int e = 0; e < 4; e++) o[j][e] = 0.0f;
    float m0 = -1e30f, m1 = -1e30f, l0 = 0.0f, l1 = 0.0f;

    const int grow = q0 + 16 * wid + (lane >> 2);
    const int* mrow0 = mask + ((size_t)b * SEQ + grow) * SEQ;
    const int* mrow1 = mrow0 + 8 * SEQ;

    const int brow = (lane & 7) + ((lane >> 4) << 3);
    const unsigned bxor = (unsigned)((brow & 7) << 4);
    const unsigned bhi = (unsigned)((lane >> 3) & 1);
    const int vtt = lane >> 3;
    const int vrow_lo = ((vtt & 1) << 3) + (lane & 7);
    const unsigned vch_add = (unsigned)(vtt >> 1);

    for (int n = 0; n < SEQ / ATT_BN; n++) {
        const int j0 = n * ATT_BN;
        const int cur = n & 1;
        if (n > 0) {
            cp_wait0();
            __syncthreads();
        }
        if (n + 1 < SEQ / ATT_BN) {
            char* bufn = base + (cur ^ 1) * ATT_BUF_B;
            const int jn = j0 + ATT_BN;
#pragma unroll
            for (int i = 0; i < 4; i++) {
                const int idx = tid + 256 * i;
                const int t = idx >> 9;
                const int idx2 = idx & 511;
                const int r = idx2 >> 3, cc = idx2 & 7;
                const unsigned* src = t ? g_Vf : g_Kf;
                const size_t gi =
                    (size_t)(b * SEQ + jn + r) * DM2 + h * 32 + cc * 4;
                char* dst =
                    bufn + t * ATT_TILE_B + r * 128 + ((cc ^ (r & 7)) << 4);
                cp_async16(dst, src + gi);
            }
            cp_commit();
        }

        const unsigned sKf = sbase + (unsigned)cur * ATT_BUF_B;
        const unsigned sVf = sKf + ATT_TILE_B;

        // ---- S = Q.K^T (single fp16 MMA) ----
        float c[8][4];
#pragma unroll
        for (int j = 0; j < 8; j++)
#pragma unroll
            for (int e = 0; e < 4; e++) c[j][e] = 0.0f;

#pragma unroll
        for (int ks = 0; ks < 4; ks++) {
#pragma unroll
            for (int j2 = 0; j2 < 4; j2++) {
                const int kr = 16 * j2 + brow;
                const unsigned off = (unsigned)(kr * 128) +
                    ((((unsigned)(2 * ks) + bhi) << 4) ^ bxor);
                unsigned kb[4];
                ldmx4(kb, sKf + off);
                mma_f16(c[2 * j2],     qf[ks], kb[0], kb[1]);
                mma_f16(c[2 * j2 + 1], qf[ks], kb[2], kb[3]);
            }
        }

        // ---- scale + mask ----
        const int mcol = j0 + 2 * (lane & 3);
#pragma unroll
        for (int j = 0; j < 8; j++) {
            const int2 mv0 = *(const int2*)(mrow0 + mcol + 8 * j);
            const int2 mv1 = *(const int2*)(mrow1 + mcol + 8 * j);
            c[j][0] = mv0.x ? c[j][0] * 0.125f : -1e9f;
            c[j][1] = mv0.y ? c[j][1] * 0.125f : -1e9f;
            c[j][2] = mv1.x ? c[j][2] * 0.125f : -1e9f;
            c[j][3] = mv1.y ? c[j][3] * 0.125f : -1e9f;
        }

        // ---- row max (quad shuffle reduce) ----
        float t0 = -1e30f, t1 = -1e30f;
#pragma unroll
        for (int j = 0; j < 8; j++) {
            t0 = fmaxf(t0, fmaxf(c[j][0], c[j][1]));
            t1 = fmaxf(t1, fmaxf(c[j][2], c[j][3]));
        }
        t0 = fmaxf(t0, __shfl_xor_sync(0xffffffffu, t0, 1));
        t0 = fmaxf(t0, __shfl_xor_sync(0xffffffffu, t0, 2));
        t1 = fmaxf(t1, __shfl_xor_sync(0xffffffffu, t1, 1));
        t1 = fmaxf(t1, __shfl_xor_sync(0xffffffffu, t1, 2));

        const float mn0 = fmaxf(m0, t0);
        const float mn1 = fmaxf(m1, t1);
        const float al0 = __expf(m0 - mn0);
        const float al1 = __expf(m1 - mn1);
        m0 = mn0; m1 = mn1;
        l0 *= al0; l1 *= al1;
#pragma unroll
        for (int j = 0; j < 8; j++) {
            o[j][0] *= al0; o[j][1] *= al0;
            o[j][2] *= al1; o[j][3] *= al1;
        }

        // ---- exponentiate, accumulate row sums ----
#pragma unroll
        for (int j = 0; j < 8; j++) {
            c[j][0] = __expf(c[j][0] - m0);
            c[j][1] = __expf(c[j][1] - m0);
            c[j][2] = __expf(c[j][2] - m1);
            c[j][3] = __expf(c[j][3] - m1);
            l0 += c[j][0] + c[j][1];
            l1 += c[j][2] + c[j][3];
        }

        // ---- O += P.V (register repack to fp16 A-fragment) ----
#pragma unroll
        for (int kk = 0; kk < 4; kk++) {
            unsigned paf[4];
            paf[0] = pack_f16(c[2 * kk][0],     c[2 * kk][1]);
            paf[1] = pack_f16(c[2 * kk][2],     c[2 * kk][3]);
            paf[2] = pack_f16(c[2 * kk + 1][0], c[2 * kk + 1][1]);
            paf[3] = pack_f16(c[2 * kk + 1][2], c[2 * kk + 1][3]);
#pragma unroll
            for (int j2 = 0; j2 < 4; j2++) {
                const int vr = 16 * kk + vrow_lo;
                const unsigned ch = 2 * (unsigned)j2 + vch_add;
                const unsigned off = (unsigned)(vr * 128) +
                    ((ch ^ (unsigned)(vr & 7)) << 4);
                unsigned vb[4];
                ldmx4t(vb, sVf + off);
                mma_f16(o[2 * j2],     paf, vb[0], vb[1]);
                mma_f16(o[2 * j2 + 1], paf, vb[2], vb[3]);
            }
        }
    }

    // ---- finalize: normalize, write X as bf16 hi/lo ----
    l0 += __shfl_xor_sync(0xffffffffu, l0, 1);
    l0 += __shfl_xor_sync(0xffffffffu, l0, 2);
    l1 += __shfl_xor_sync(0xffffffffu, l1, 1);
    l1 += __shfl_xor_sync(0xffffffffu, l1, 2);
    const float inv0 = 1.0f / l0;
    const float inv1 = 1.0f / l1;

    const size_t xrow = (size_t)(b * SEQ + grow) * DM2 + h * 32 + (lane & 3);
#pragma unroll
    for (int j = 0; j < 8; j++) {
        unsigned h0, lo0, h1, lo1;
        cvt_split2(o[j][0] * inv0, o[j][1] * inv0, h0, lo0);
        cvt_split2(o[j][2] * inv1, o[j][3] * inv1, h1, lo1);
        g_Xh[xrow + 4 * j] = h0;
        g_Xl[xrow + 4 * j] = lo0;
        g_Xh[xrow + 8 * DM2 + 4 * j] = h1;
        g_Xl[xrow + 8 * DM2 + 4 * j] = lo1;
    }
}

// ---------------------------------------------------------------------------
// Launch
// Inputs (metadata order): q, k, v, w_q, w_k, w_v, w_o, mask
// ---------------------------------------------------------------------------
extern "C" void kernel_launch(void* const* d_in, const int* in_sizes, int n_in,
                              void* d_out, int out_size) {
    const float* q  = (const float*)d_in[0];
    const float* k  = (const float*)d_in[1];
    const float* v  = (const float*)d_in[2];
    const float* wq = (const float*)d_in[3];
    const float* wk = (const float*)d_in[4];
    const float* wv = (const float*)d_in[5];
    const float* wo = (const float*)d_in[6];
    const int* mask = (const int*)d_in[7];
    float* out = (float*)d_out;

    cudaFuncSetAttribute(mha_gemm_qkv,
                         cudaFuncAttributeMaxDynamicSharedMemorySize, GEMM_SMEM);
    cudaFuncSetAttribute(mha_gemm_out,
                         cudaFuncAttributeMaxDynamicSharedMemorySize, GEMM_SMEM);
    cudaFuncSetAttribute(mha_flash_attn_tc,
                         cudaFuncAttributeMaxDynamicSharedMemorySize, ATT_SMEM);

    // 0) pre-split weights to bf16 hi/lo
    dim3 gw(512, 4);
    presplit_w<<<gw, 256>>>(wq, wk, wv, wo);

    // 1) Q/K/V projections (3-way bf16), writing fp16 Q/K/V
    dim3 gqkv(DMODEL / 128, MROWS / 128, 3);
    mha_gemm_qkv<<<gqkv, 512, GEMM_SMEM>>>(q, k, v);

    // 2) fp16 flash attention
    dim3 gatt(SEQ / ATT_BM, BATCH * NHEAD);
    mha_flash_attn_tc<<<gatt, 256, ATT_SMEM>>>(mask);

    // 3) output projection (3-way bf16)
    dim3 gout(DMODEL / 128, MROWS / 128, 1);
    mha_gemm_out<<<gout, 512, GEMM_SMEM>>>(out);
}

// round 15
// speedup vs baseline: 1.7798x; 1.2956x over previous
#include <cuda_runtime.h>
#include <cuda_bf16.h>

// Problem constants
#define BATCH   2
#define SEQ     2048
#define DMODEL  1024
#define NHEAD   16
#define DK      64
#define MROWS   (BATCH * SEQ)       // 4096
#define DM2     (DMODEL / 2)        // u32 (16-bit pair) per row
#define WU4     (DMODEL * DMODEL / 8)  // uint4 per weight matrix (131072)

// ---------------------------------------------------------------------------
// Scratch: Q/K/V fp16; X bf16 hi/lo; W: q/k/v fp16, w_o bf16 hi/lo
// ---------------------------------------------------------------------------
__device__ unsigned g_Qf[MROWS * DM2];
__device__ unsigned g_Kf[MROWS * DM2];
__device__ unsigned g_Vf[MROWS * DM2];
__device__ unsigned g_Xh[MROWS * DM2], g_Xl[MROWS * DM2];
__device__ unsigned g_Wf[3 * DMODEL * DM2];            // fp16 wq/wk/wv
__device__ unsigned g_Woh[DMODEL * DM2], g_Wol[DMODEL * DM2];

// ---------------------------------------------------------------------------
// Warp-level tensor core helpers (sm_80-baseline PTX: works on plain sm_103)
// ---------------------------------------------------------------------------
__device__ __forceinline__ unsigned smem_u32(const void* p) {
    return (unsigned)__cvta_generic_to_shared(p);
}
__device__ __forceinline__ void ldmx4(unsigned* r, unsigned addr) {
    asm volatile(
        "ldmatrix.sync.aligned.m8n8.x4.shared.b16 {%0,%1,%2,%3}, [%4];"
        : "=r"(r[0]), "=r"(r[1]), "=r"(r[2]), "=r"(r[3]) : "r"(addr));
}
__device__ __forceinline__ void ldmx4t(unsigned* r, unsigned addr) {
    asm volatile(
        "ldmatrix.sync.aligned.m8n8.x4.trans.shared.b16 {%0,%1,%2,%3}, [%4];"
        : "=r"(r[0]), "=r"(r[1]), "=r"(r[2]), "=r"(r[3]) : "r"(addr));
}
__device__ __forceinline__ void mma_bf16(float* d, const unsigned* a,
                                         unsigned b0, unsigned b1) {
    asm volatile(
        "mma.sync.aligned.m16n8k16.row.col.f32.bf16.bf16.f32 "
        "{%0,%1,%2,%3}, {%4,%5,%6,%7}, {%8,%9}, {%0,%1,%2,%3};"
        : "+f"(d[0]), "+f"(d[1]), "+f"(d[2]), "+f"(d[3])
        : "r"(a[0]), "r"(a[1]), "r"(a[2]), "r"(a[3]), "r"(b0), "r"(b1));
}
__device__ __forceinline__ void mma_f16(float* d, const unsigned* a,
                                        unsigned b0, unsigned b1) {
    asm volatile(
        "mma.sync.aligned.m16n8k16.row.col.f32.f16.f16.f32 "
        "{%0,%1,%2,%3}, {%4,%5,%6,%7}, {%8,%9}, {%0,%1,%2,%3};"
        : "+f"(d[0]), "+f"(d[1]), "+f"(d[2]), "+f"(d[3])
        : "r"(a[0]), "r"(a[1]), "r"(a[2]), "r"(a[3]), "r"(b0), "r"(b1));
}

// fp32 pair -> bf16x2 hi + bf16x2 lo
__device__ __forceinline__ void cvt_split2(float x0, float x1,
                                           unsigned& h, unsigned& l) {
    asm("cvt.rn.satfinite.bf16x2.f32 %0, %1, %2;" : "=r"(h) : "f"(x1), "f"(x0));
    float hf0 = __uint_as_float(h << 16);
    float hf1 = __uint_as_float(h & 0xffff0000u);
    float l0 = x0 - hf0;
    float l1 = x1 - hf1;
    asm("cvt.rn.satfinite.bf16x2.f32 %0, %1, %2;" : "=r"(l) : "f"(l1), "f"(l0));
}
// fp32 pair -> fp16x2 (lo half = x0)
__device__ __forceinline__ unsigned pack_f16(float x0, float x1) {
    unsigned r;
    asm("cvt.rn.f16x2.f32 %0, %1, %2;" : "=r"(r) : "f"(x1), "f"(x0));
    return r;
}
__device__ __forceinline__ void split_store(float4 a, float4 b,
                                            char* dst_hi, char* dst_lo) {
    uint4 h, l;
    cvt_split2(a.x, a.y, h.x, l.x);
    cvt_split2(a.z, a.w, h.y, l.y);
    cvt_split2(b.x, b.y, h.z, l.z);
    cvt_split2(b.z, b.w, h.w, l.w);
    *(uint4*)dst_hi = h;
    *(uint4*)dst_lo = l;
}

// cp.async 16B (bypass-L1)
__device__ __forceinline__ void cp_async16(void* smem_ptr, const void* gptr) {
    unsigned saddr = (unsigned)__cvta_generic_to_shared(smem_ptr);
    asm volatile("cp.async.cg.shared.global [%0], [%1], 16;"
                 :: "r"(saddr), "l"(gptr) : "memory");
}
__device__ __forceinline__ void cp_commit() {
    asm volatile("cp.async.commit_group;" ::: "memory");
}
__device__ __forceinline__ void cp_wait0() {
    asm volatile("cp.async.wait_group 0;" ::: "memory");
}
__device__ __forceinline__ void cp_wait1() {
    asm volatile("cp.async.wait_group 1;" ::: "memory");
}

// ---------------------------------------------------------------------------
// Weight prep: wq/wk/wv -> fp16; wo -> bf16 hi/lo
// ---------------------------------------------------------------------------
__global__ void __launch_bounds__(256)
presplit_w(const float* __restrict__ w0, const float* __restrict__ w1,
           const float* __restrict__ w2, const float* __restrict__ w3) {
    const int m = blockIdx.y;
    const float* src = (m == 0) ? w0 : (m == 1) ? w1 : (m == 2) ? w2 : w3;
    const int gid = blockIdx.x * 256 + threadIdx.x;   // 0..131071
    const float4* s4 = (const float4*)src;
    float4 a = s4[2 * gid], b = s4[2 * gid + 1];
    if (m < 3) {
        uint4 f;
        f.x = pack_f16(a.x, a.y);
        f.y = pack_f16(a.z, a.w);
        f.z = pack_f16(b.x, b.y);
        f.w = pack_f16(b.z, b.w);
        ((uint4*)g_Wf)[(size_t)m * WU4 + gid] = f;
    } else {
        uint4 h, l;
        cvt_split2(a.x, a.y, h.x, l.x);
        cvt_split2(a.z, a.w, h.y, l.y);
        cvt_split2(b.x, b.y, h.z, l.z);
        cvt_split2(b.z, b.w, h.w, l.w);
        ((uint4*)g_Woh)[gid] = h;
        ((uint4*)g_Wol)[gid] = l;
    }
}

// ---------------------------------------------------------------------------
// fp16 single-MMA NT GEMM (QKV projections): C[m,n] = sum_k A[m,k]*W[n,k].
// CTA 128x128, 512 threads, 16 warps (4x4, warp 32x32), K staged 64/stage,
// cp.async double-buffered B (fp16 weights), A converted fp32->fp16 in-loop.
// ---------------------------------------------------------------------------
#define GF_TILE_BYTES (128 * 64 * 2)            // 16 KB (f16 tile)
#define GF_BUF_BYTES (2 * GF_TILE_BYTES)        // A + B = 32 KB
#define GEMMF_SMEM (2 * GF_BUF_BYTES + 1024)
#define GK_STAGES 16

__global__ void __launch_bounds__(512, 1)
mha_gemm_qkv_f16(const float* __restrict__ q, const float* __restrict__ k,
                 const float* __restrict__ v) {
    const int z = blockIdx.z;
    const float* A = (z == 0) ? q : (z == 1) ? k : v;
    const unsigned* Wf = g_Wf + (size_t)z * DMODEL * DM2;
    unsigned* Cf = (z == 0) ? g_Qf : (z == 1) ? g_Kf : g_Vf;

    extern __shared__ char dyn_raw[];
    char* dynb = (char*)(((unsigned long long)(size_t)dyn_raw + 1023ull) &
                         ~1023ull);
    const unsigned sbase = smem_u32(dynb);

    const int tid = threadIdx.x;
    const int wid = tid >> 5;
    const int lane = tid & 31;
    const int m0 = blockIdx.y * 128;
    const int n0 = blockIdx.x * 128;

    const float4* A4 = (const float4*)A;

    const int rb = tid >> 3;      // 0..63
    const int cc = tid & 7;

    const int wm = (wid >> 2) * 32;
    const int wn = (wid & 3) * 32;
    const int arow = lane & 15;
    const unsigned ahi = (unsigned)(lane >> 4);
    const unsigned axor = (unsigned)((arow & 7) << 4);
    const int brow = (lane & 7) + ((lane >> 4) << 3);
    const unsigned bxor = (unsigned)((brow & 7) << 4);
    const unsigned bhi = (unsigned)((lane >> 3) & 1);

    float d[2][4][4];
#pragma unroll
    for (int i = 0; i < 2; i++)
#pragma unroll
        for (int j = 0; j < 4; j++)
#pragma unroll
            for (int e = 0; e < 4; e++) d[i][j][e] = 0.0f;

    float4 ra[2][2];

#define FBUF(b) (dynb + (b) * GF_BUF_BYTES)

#define GF_LDGA(s)                                                         \
    do {                                                                   \
        _Pragma("unroll")                                                  \
        for (int i = 0; i < 2; i++) {                                      \
            const size_t ga =                                              \
                (size_t)(m0 + rb + 64 * i) * 256 + (s) * 16 + cc * 2;      \
            ra[i][0] = A4[ga];                                             \
            ra[i][1] = A4[ga + 1];                                         \
        } } while (0)

#define GF_STSA(b)                                                         \
    do {                                                                   \
        char* Ap = FBUF(b);                                                \
        _Pragma("unroll")                                                  \
        for (int i = 0; i < 2; i++) {                                      \
            const int r = rb + 64 * i;                                     \
            const unsigned sw = (unsigned)(r * 128) +                      \
                (((unsigned)cc ^ (unsigned)(r & 7)) << 4);                 \
            uint4 f;                                                       \
            f.x = pack_f16(ra[i][0].x, ra[i][0].y);                        \
            f.y = pack_f16(ra[i][0].z, ra[i][0].w);                        \
            f.z = pack_f16(ra[i][1].x, ra[i][1].y);                        \
            f.w = pack_f16(ra[i][1].z, ra[i][1].w);                        \
            *(uint4*)(Ap + sw) = f;                                        \
        } } while (0)

#define GF_CPB(s, b)                                                       \
    do {                                                                   \
        _Pragma("unroll")                                                  \
        for (int i = 0; i < 2; i++) {                                      \
            const int idx = tid + 512 * i;                                 \
            const int r2 = idx >> 3, c2 = idx & 7;                         \
            cp_async16(FBUF(b) + GF_TILE_BYTES + r2 * 128 +                \
                           (((unsigned)c2 ^ (unsigned)(r2 & 7)) << 4),     \
                       Wf + (size_t)(n0 + r2) * DM2 + (s) * 32 + c2 * 4);  \
        } } while (0)

    GF_LDGA(0);
    GF_CPB(0, 0);
    cp_commit();
    GF_STSA(0);
    GF_LDGA(1);

    for (int s = 0; s < GK_STAGES; s++) {
        const int cur = s & 1;
        if (s + 1 < GK_STAGES) {
            GF_CPB(s + 1, cur ^ 1);
            cp_commit();
            GF_STSA(cur ^ 1);
            if (s + 2 < GK_STAGES) GF_LDGA(s + 2);
            cp_wait1();
        } else {
            cp_wait0();
        }
        __syncthreads();

        const unsigned bo = sbase + (unsigned)cur * GF_BUF_BYTES;
        const unsigned sA = bo;
        const unsigned sB = bo + GF_TILE_BYTES;
#pragma unroll
        for (int ks = 0; ks < 4; ks++) {
            unsigned bf[2][4];
#pragma unroll
            for (int j2 = 0; j2 < 2; j2++) {
                const unsigned roff =
                    (unsigned)(wn + 16 * j2 + brow) * 128 +
                    ((((unsigned)(2 * ks) + bhi) << 4) ^ bxor);
                ldmx4(bf[j2], sB + roff);
            }
#pragma unroll
            for (int i = 0; i < 2; i++) {
                const unsigned aoff =
                    (unsigned)(wm + 16 * i + arow) * 128 +
                    ((((unsigned)(2 * ks) + ahi) << 4) ^ axor);
                unsigned af[4];
                ldmx4(af, sA + aoff);
#pragma unroll
                for (int j = 0; j < 4; j++)
                    mma_f16(d[i][j], af, bf[j >> 1][(j & 1) * 2],
                            bf[j >> 1][(j & 1) * 2 + 1]);
            }
        }
        __syncthreads();
    }
#undef GF_LDGA
#undef GF_STSA
#undef GF_CPB
#undef FBUF

    // ---- epilogue: fp16 out ----
    const int r0 = m0 + wm + (lane >> 2);
    const int cb = n0 + wn + 2 * (lane & 3);
#pragma unroll
    for (int i = 0; i < 2; i++)
#pragma unroll
        for (int j = 0; j < 4; j++) {
            const unsigned p0 = pack_f16(d[i][j][0], d[i][j][1]);
            const unsigned p1 = pack_f16(d[i][j][2], d[i][j][3]);
            const size_t idx = (size_t)(r0 + 16 * i) * DM2 + (cb >> 1) + 4 * j;
            Cf[idx] = p0;
            Cf[idx + 8 * DM2] = p1;
        }
}

// ---------------------------------------------------------------------------
// 3-way bf16 split NT GEMM (output projection, verified): A pre-split X,
// W pre-split wo, fp32 out. CTA 128x128, 512 threads, cp.async double-buffer.
// ---------------------------------------------------------------------------
#define GK_TILE_BYTES (128 * 64 * 2)            // 16 KB per tensor-half
#define GK_BUF_BYTES (4 * GK_TILE_BYTES)        // Ah, Al, Bh, Bl = 64 KB
#define GEMM_SMEM (2 * GK_BUF_BYTES + 1024)

__global__ void __launch_bounds__(512, 1)
mha_gemm_out(float* __restrict__ out) {
    const uint4* Ah4 = (const uint4*)g_Xh;
    const uint4* Al4 = (const uint4*)g_Xl;
    const uint4* Wh4 = (const uint4*)g_Woh;
    const uint4* Wl4 = (const uint4*)g_Wol;

    extern __shared__ char dyn_raw[];
    char* dynb = (char*)(((unsigned long long)(size_t)dyn_raw + 1023ull) &
                         ~1023ull);
    const unsigned sbase = smem_u32(dynb);

    const int tid = threadIdx.x;
    const int wid = tid >> 5;
    const int lane = tid & 31;
    const int m0 = blockIdx.y * 128;
    const int n0 = blockIdx.x * 128;

    const int wm = (wid >> 2) * 32;
    const int wn = (wid & 3) * 32;
    const int arow = lane & 15;
    const unsigned ahi = (unsigned)(lane >> 4);
    const unsigned axor = (unsigned)((arow & 7) << 4);
    const int brow = (lane & 7) + ((lane >> 4) << 3);
    const unsigned bxor = (unsigned)((brow & 7) << 4);
    const unsigned bhi = (unsigned)((lane >> 3) & 1);

    float d[2][4][4];
#pragma unroll
    for (int i = 0; i < 2; i++)
#pragma unroll
        for (int j = 0; j < 4; j++)
#pragma unroll
            for (int e = 0; e < 4; e++) d[i][j][e] = 0.0f;

#define GBUF(b) (dynb + (b) * GK_BUF_BYTES)

#define GO_CP(s, b)                                                        \
    do {                                                                   \
        _Pragma("unroll")                                                  \
        for (int t = 0; t < 4; t++) {                                      \
            const uint4* srcp = (t == 0) ? Ah4 : (t == 1) ? Al4            \
                                : (t == 2) ? Wh4 : Wl4;                    \
            const int base_rc = (t < 2) ? m0 : n0;                         \
            _Pragma("unroll")                                              \
            for (int i = 0; i < 2; i++) {                                  \
                const int idx = tid + 512 * i;                             \
                const int r2 = idx >> 3, c2 = idx & 7;                     \
                cp_async16(GBUF(b) + t * GK_TILE_BYTES + r2 * 128 +        \
                               (((unsigned)c2 ^ (unsigned)(r2 & 7)) << 4), \
                           srcp + (size_t)(base_rc + r2) * 128 +           \
                               (s) * 8 + c2);                              \
            } } } while (0)

    GO_CP(0, 0);
    cp_commit();

    for (int s = 0; s < GK_STAGES; s++) {
        const int cur = s & 1;
        if (s + 1 < GK_STAGES) {
            GO_CP(s + 1, cur ^ 1);
            cp_commit();
            cp_wait1();
        } else {
            cp_wait0();
        }
        __syncthreads();

        const unsigned bo = sbase + (unsigned)cur * GK_BUF_BYTES;
        const unsigned sAh = bo;
        const unsigned sAl = bo + GK_TILE_BYTES;
        const unsigned sBh = bo + 2 * GK_TILE_BYTES;
        const unsigned sBl = bo + 3 * GK_TILE_BYTES;
#pragma unroll
        for (int ks = 0; ks < 4; ks++) {
            unsigned bh[2][4], bl[2][4];
#pragma unroll
            for (int j2 = 0; j2 < 2; j2++) {
                const unsigned roff =
                    (unsigned)(wn + 16 * j2 + brow) * 128 +
                    ((((unsigned)(2 * ks) + bhi) << 4) ^ bxor);
                ldmx4(bh[j2], sBh + roff);
                ldmx4(bl[j2], sBl + roff);
            }
#pragma unroll
            for (int i = 0; i < 2; i++) {
                const unsigned aoff =
                    (unsigned)(wm + 16 * i + arow) * 128 +
                    ((((unsigned)(2 * ks) + ahi) << 4) ^ axor);
                unsigned ah[4], al[4];
                ldmx4(ah, sAh + aoff);
                ldmx4(al, sAl + aoff);
#pragma unroll
                for (int j = 0; j < 4; j++) {
                    const unsigned b0h = bh[j >> 1][(j & 1) * 2];
                    const unsigned b1h = bh[j >> 1][(j & 1) * 2 + 1];
                    const unsigned b0l = bl[j >> 1][(j & 1) * 2];
                    const unsigned b1l = bl[j >> 1][(j & 1) * 2 + 1];
                    mma_bf16(d[i][j], ah, b0h, b1h);
                    mma_bf16(d[i][j], ah, b0l, b1l);
                    mma_bf16(d[i][j], al, b0h, b1h);
                }
            }
        }
        __syncthreads();
    }
#undef GO_CP
#undef GBUF

    const int r0 = m0 + wm + (lane >> 2);
    const int cb = n0 + wn + 2 * (lane & 3);
    float* Cbase = out + (size_t)r0 * DMODEL + cb;
#pragma unroll
    for (int i = 0; i < 2; i++)
#pragma unroll
        for (int j = 0; j < 4; j++) {
            *(float2*)(Cbase + (size_t)(16 * i) * DMODEL + 8 * j) =
                make_float2(d[i][j][0], d[i][j][1]);
            *(float2*)(Cbase + (size_t)(16 * i + 8) * DMODEL + 8 * j) =
                make_float2(d[i][j][2], d[i][j][3]);
        }
}

// ---------------------------------------------------------------------------
// fp16 single-pass tensor-core flash attention (verified R14, unchanged).
// ---------------------------------------------------------------------------
#define ATT_BM 128
#define ATT_BN 64
#define ATT_TILE_B (ATT_BN * 128)            // 8 KB: 64 rows x 128B fp16
#define ATT_BUF_B (2 * ATT_TILE_B)           // Kf + Vf = 16 KB per buffer
#define ATT_SMEM (2 * ATT_BUF_B + 1024)      // ~33 KB

__global__ void __launch_bounds__(256)
mha_flash_attn_tc(const int* __restrict__ mask) {
    extern __shared__ char att_raw[];
    char* base = (char*)(((unsigned long long)(size_t)att_raw + 1023ull) &
                         ~1023ull);
    const unsigned sbase = smem_u32(base);

    const int tid = threadIdx.x;
    const int wid = tid >> 5;
    const int lane = tid & 31;
    const int q0 = blockIdx.x * ATT_BM;
    const int bh = blockIdx.y;
    const int b = bh >> 4;
    const int h = bh & 15;

    // ---- prologue: K/V tile 0 -> buf0; Q -> buf1 region ----
#pragma unroll
    for (int i = 0; i < 4; i++) {
        const int idx = tid + 256 * i;
        const int t = idx >> 9;                 // 0: K, 1: V
        const int idx2 = idx & 511;
        const int r = idx2 >> 3, cc = idx2 & 7;
        const unsigned* src = t ? g_Vf : g_Kf;
        const size_t gi = (size_t)(b * SEQ + r) * DM2 + h * 32 + cc * 4;
        char* dst = base + t * ATT_TILE_B + r * 128 + ((cc ^ (r & 7)) << 4);
        cp_async16(dst, src + gi);
    }
#pragma unroll
    for (int i = 0; i < 4; i++) {
        const int idx = tid + 256 * i;
        const int r = idx >> 3, cc = idx & 7;
        const size_t gi = (size_t)(b * SEQ + q0 + r) * DM2 + h * 32 + cc * 4;
        char* dst = base + ATT_BUF_B + r * 128 + ((cc ^ (r & 7)) << 4);
        cp_async16(dst, g_Qf + gi);
    }
    cp_commit();
    cp_wait0();
    __syncthreads();

    // ---- Q fragments (registers, whole kernel) ----
    unsigned qf[4][4];
    {
        const int arow = lane & 15;
        const unsigned ahi = (unsigned)(lane >> 4);
        const int row = 16 * wid + arow;
#pragma unroll
        for (int kk = 0; kk < 4; kk++) {
            const unsigned ch = 2 * (unsigned)kk + ahi;
            const unsigned off =
                (unsigned)(row * 128) + ((ch ^ (unsigned)(row & 7)) << 4);
            ldmx4(qf[kk], sbase + ATT_BUF_B + off);
        }
    }
    __syncthreads();

    float o[8][4];
#pragma unroll
    for (int j = 0; j < 8; j++)
#pragma unroll
        for (int e = 0; e < 4; e++) o[j][e] = 0.0f;
    float m0 = -1e30f, m1 = -1e30f, l0 = 0.0f, l1 = 0.0f;

    const int grow = q0 + 16 * wid + (lane >> 2);
    const int* mrow0 = mask + ((size_t)b * SEQ + grow) * SEQ;
    const int* mrow1 = mrow0 + 8 * SEQ;

    const int brow = (lane & 7) + ((lane >> 4) << 3);
    const unsigned bxor = (unsigned)((brow & 7) << 4);
    const unsigned bhi = (unsigned)((lane >> 3) & 1);
    const int vtt = lane >> 3;
    const int vrow_lo = ((vtt & 1) << 3) + (lane & 7);
    const unsigned vch_add = (unsigned)(vtt >> 1);

    for (int n = 0; n < SEQ / ATT_BN; n++) {
        const int j0 = n * ATT_BN;
        const int cur = n & 1;
        if (n > 0) {
            cp_wait0();
            __syncthreads();
        }
        if (n + 1 < SEQ / ATT_BN) {
            char* bufn = base + (cur ^ 1) * ATT_BUF_B;
            const int jn = j0 + ATT_BN;
#pragma unroll
            for (int i = 0; i < 4; i++) {
                const int idx = tid + 256 * i;
                const int t = idx >> 9;
                const int idx2 = idx & 511;
                const int r = idx2 >> 3, cc = idx2 & 7;
                const unsigned* src = t ? g_Vf : g_Kf;
                const size_t gi =
                    (size_t)(b * SEQ + jn + r) * DM2 + h * 32 + cc * 4;
                char* dst =
                    bufn + t * ATT_TILE_B + r * 128 + ((cc ^ (r & 7)) << 4);
                cp_async16(dst, src + gi);
            }
            cp_commit();
        }

        const unsigned sKf = sbase + (unsigned)cur * ATT_BUF_B;
        const unsigned sVf = sKf + ATT_TILE_B;

        // ---- S = Q.K^T ----
        float c[8][4];
#pragma unroll
        for (int j = 0; j < 8; j++)
#pragma unroll
            for (int e = 0; e < 4; e++) c[j][e] = 0.0f;

#pragma unroll
        for (int ks = 0; ks < 4; ks++) {
#pragma unroll
            for (int j2 = 0; j2 < 4; j2++) {
                const int kr = 16 * j2 + brow;
                const unsigned off = (unsigned)(kr * 128) +
                    ((((unsigned)(2 * ks) + bhi) << 4) ^ bxor);
                unsigned kb[4];
                ldmx4(kb, sKf + off);
                mma_f16(c[2 * j2],     qf[ks], kb[0], kb[1]);
                mma_f16(c[2 * j2 + 1], qf[ks], kb[2], kb[3]);
            }
        }

        // ---- scale + mask ----
        const int mcol = j0 + 2 * (lane & 3);
#pragma unroll
        for (int j = 0; j < 8; j++) {
            const int2 mv0 = *(const int2*)(mrow0 + mcol + 8 * j);
            const int2 mv1 = *(const int2*)(mrow1 + mcol + 8 * j);
            c[j][0] = mv0.x ? c[j][0] * 0.125f : -1e9f;
            c[j][1] = mv0.y ? c[j][1] * 0.125f : -1e9f;
            c[j][2] = mv1.x ? c[j][2] * 0.125f : -1e9f;
            c[j][3] = mv1.y ? c[j][3] * 0.125f : -1e9f;
        }

        // ---- row max ----
        float t0 = -1e30f, t1 = -1e30f;
#pragma unroll
        for (int j = 0; j < 8; j++) {
            t0 = fmaxf(t0, fmaxf(c[j][0], c[j][1]));
            t1 = fmaxf(t1, fmaxf(c[j][2], c[j][3]));
        }
        t0 = fmaxf(t0, __shfl_xor_sync(0xffffffffu, t0, 1));
        t0 = fmaxf(t0, __shfl_xor_sync(0xffffffffu, t0, 2));
        t1 = fmaxf(t1, __shfl_xor_sync(0xffffffffu, t1, 1));
        t1 = fmaxf(t1, __shfl_xor_sync(0xffffffffu, t1, 2));

        const float mn0 = fmaxf(m0, t0);
        const float mn1 = fmaxf(m1, t1);
        const float al0 = __expf(m0 - mn0);
        const float al1 = __expf(m1 - mn1);
        m0 = mn0; m1 = mn1;
        l0 *= al0; l1 *= al1;
#pragma unroll
        for (int j = 0; j < 8; j++) {
            o[j][0] *= al0; o[j][1] *= al0;
            o[j][2] *= al1; o[j][3] *= al1;
        }

        // ---- exponentiate ----
#pragma unroll
        for (int j = 0; j < 8; j++) {
            c[j][0] = __expf(c[j][0] - m0);
            c[j][1] = __expf(c[j][1] - m0);
            c[j][2] = __expf(c[j][2] - m1);
            c[j][3] = __expf(c[j][3] - m1);
            l0 += c[j][0] + c[j][1];
            l1 += c[j][2] + c[j][3];
        }

        // ---- O += P.V ----
#pragma unroll
        for (int kk = 0; kk < 4; kk++) {
            unsigned paf[4];
            paf[0] = pack_f16(c[2 * kk][0],     c[2 * kk][1]);
            paf[1] = pack_f16(c[2 * kk][2],     c[2 * kk][3]);
            paf[2] = pack_f16(c[2 * kk + 1][0], c[2 * kk + 1][1]);
            paf[3] = pack_f16(c[2 * kk + 1][2], c[2 * kk + 1][3]);
#pragma unroll
            for (int j2 = 0; j2 < 4; j2++) {
                const int vr = 16 * kk + vrow_lo;
                const unsigned ch = 2 * (unsigned)j2 + vch_add;
                const unsigned off = (unsigned)(vr * 128) +
                    ((ch ^ (unsigned)(vr & 7)) << 4);
                unsigned vb[4];
                ldmx4t(vb, sVf + off);
                mma_f16(o[2 * j2],     paf, vb[0], vb[1]);
                mma_f16(o[2 * j2 + 1], paf, vb[2], vb[3]);
            }
        }
    }

    // ---- finalize: normalize, write X as bf16 hi/lo ----
    l0 += __shfl_xor_sync(0xffffffffu, l0, 1);
    l0 += __shfl_xor_sync(0xffffffffu, l0, 2);
    l1 += __shfl_xor_sync(0xffffffffu, l1, 1);
    l1 += __shfl_xor_sync(0xffffffffu, l1, 2);
    const float inv0 = 1.0f / l0;
    const float inv1 = 1.0f / l1;

    const size_t xrow = (size_t)(b * SEQ + grow) * DM2 + h * 32 + (lane & 3);
#pragma unroll
    for (int j = 0; j < 8; j++) {
        unsigned h0, lo0, h1, lo1;
        cvt_split2(o[j][0] * inv0, o[j][1] * inv0, h0, lo0);
        cvt_split2(o[j][2] * inv1, o[j][3] * inv1, h1, lo1);
        g_Xh[xrow + 4 * j] = h0;
        g_Xl[xrow + 4 * j] = lo0;
        g_Xh[xrow + 8 * DM2 + 4 * j] = h1;
        g_Xl[xrow + 8 * DM2 + 4 * j] = lo1;
    }
}

// ---------------------------------------------------------------------------
// Launch
// Inputs (metadata order): q, k, v, w_q, w_k, w_v, w_o, mask
// ---------------------------------------------------------------------------
extern "C" void kernel_launch(void* const* d_in, const int* in_sizes, int n_in,
                              void* d_out, int out_size) {
    const float* q  = (const float*)d_in[0];
    const float* k  = (const float*)d_in[1];
    const float* v  = (const float*)d_in[2];
    const float* wq = (const float*)d_in[3];
    const float* wk = (const float*)d_in[4];
    const float* wv = (const float*)d_in[5];
    const float* wo = (const float*)d_in[6];
    const int* mask = (const int*)d_in[7];
    float* out = (float*)d_out;

    cudaFuncSetAttribute(mha_gemm_qkv_f16,
                         cudaFuncAttributeMaxDynamicSharedMemorySize,
                         GEMMF_SMEM);
    cudaFuncSetAttribute(mha_gemm_out,
                         cudaFuncAttributeMaxDynamicSharedMemorySize, GEMM_SMEM);
    cudaFuncSetAttribute(mha_flash_attn_tc,
                         cudaFuncAttributeMaxDynamicSharedMemorySize, ATT_SMEM);

    // 0) weight prep: wq/wk/wv -> fp16, wo -> bf16 hi/lo
    dim3 gw(512, 4);
    presplit_w<<<gw, 256>>>(wq, wk, wv, wo);

    // 1) Q/K/V projections: fp16 single-MMA
    dim3 gqkv(DMODEL / 128, MROWS / 128, 3);
    mha_gemm_qkv_f16<<<gqkv, 512, GEMMF_SMEM>>>(q, k, v);

    // 2) fp16 flash attention
    dim3 gatt(SEQ / ATT_BM, BATCH * NHEAD);
    mha_flash_attn_tc<<<gatt, 256, ATT_SMEM>>>(mask);

    // 3) output projection (3-way bf16, protects error margin)
    dim3 gout(DMODEL / 128, MROWS / 128, 1);
    mha_gemm_out<<<gout, 512, GEMM_SMEM>>>(out);
}

// round 16
// speedup vs baseline: 1.9958x; 1.1214x over previous
#include <cuda_runtime.h>
#include <cuda_bf16.h>

// Problem constants
#define BATCH   2
#define SEQ     2048
#define DMODEL  1024
#define NHEAD   16
#define DK      64
#define MROWS   (BATCH * SEQ)       // 4096
#define DM2     (DMODEL / 2)        // u32 (16-bit pair) per row
#define WU4     (DMODEL * DMODEL / 8)  // uint4 per weight matrix (131072)

// ---------------------------------------------------------------------------
// Scratch: Q/K/V/X fp16; all four weights fp16
// ---------------------------------------------------------------------------
__device__ unsigned g_Qf[MROWS * DM2];
__device__ unsigned g_Kf[MROWS * DM2];
__device__ unsigned g_Vf[MROWS * DM2];
__device__ unsigned g_Xf[MROWS * DM2];
__device__ unsigned g_Wf[4 * DMODEL * DM2];   // fp16 wq/wk/wv/wo

// ---------------------------------------------------------------------------
// Warp-level tensor core helpers (sm_80-baseline PTX: works on plain sm_103)
// ---------------------------------------------------------------------------
__device__ __forceinline__ unsigned smem_u32(const void* p) {
    return (unsigned)__cvta_generic_to_shared(p);
}
__device__ __forceinline__ void ldmx4(unsigned* r, unsigned addr) {
    asm volatile(
        "ldmatrix.sync.aligned.m8n8.x4.shared.b16 {%0,%1,%2,%3}, [%4];"
        : "=r"(r[0]), "=r"(r[1]), "=r"(r[2]), "=r"(r[3]) : "r"(addr));
}
__device__ __forceinline__ void ldmx4t(unsigned* r, unsigned addr) {
    asm volatile(
        "ldmatrix.sync.aligned.m8n8.x4.trans.shared.b16 {%0,%1,%2,%3}, [%4];"
        : "=r"(r[0]), "=r"(r[1]), "=r"(r[2]), "=r"(r[3]) : "r"(addr));
}
__device__ __forceinline__ void mma_f16(float* d, const unsigned* a,
                                        unsigned b0, unsigned b1) {
    asm volatile(
        "mma.sync.aligned.m16n8k16.row.col.f32.f16.f16.f32 "
        "{%0,%1,%2,%3}, {%4,%5,%6,%7}, {%8,%9}, {%0,%1,%2,%3};"
        : "+f"(d[0]), "+f"(d[1]), "+f"(d[2]), "+f"(d[3])
        : "r"(a[0]), "r"(a[1]), "r"(a[2]), "r"(a[3]), "r"(b0), "r"(b1));
}

// fp32 pair -> fp16x2 (lo half = x0)
__device__ __forceinline__ unsigned pack_f16(float x0, float x1) {
    unsigned r;
    asm("cvt.rn.f16x2.f32 %0, %1, %2;" : "=r"(r) : "f"(x1), "f"(x0));
    return r;
}

// cp.async 16B (bypass-L1)
__device__ __forceinline__ void cp_async16(void* smem_ptr, const void* gptr) {
    unsigned saddr = (unsigned)__cvta_generic_to_shared(smem_ptr);
    asm volatile("cp.async.cg.shared.global [%0], [%1], 16;"
                 :: "r"(saddr), "l"(gptr) : "memory");
}
__device__ __forceinline__ void cp_commit() {
    asm volatile("cp.async.commit_group;" ::: "memory");
}
__device__ __forceinline__ void cp_wait0() {
    asm volatile("cp.async.wait_group 0;" ::: "memory");
}
__device__ __forceinline__ void cp_wait1() {
    asm volatile("cp.async.wait_group 1;" ::: "memory");
}

// ---------------------------------------------------------------------------
// Weight prep: all four weights -> fp16
// ---------------------------------------------------------------------------
__global__ void __launch_bounds__(256)
presplit_w(const float* __restrict__ w0, const float* __restrict__ w1,
           const float* __restrict__ w2, const float* __restrict__ w3) {
    const int m = blockIdx.y;
    const float* src = (m == 0) ? w0 : (m == 1) ? w1 : (m == 2) ? w2 : w3;
    const int gid = blockIdx.x * 256 + threadIdx.x;   // 0..131071
    const float4* s4 = (const float4*)src;
    float4 a = s4[2 * gid], b = s4[2 * gid + 1];
    uint4 f;
    f.x = pack_f16(a.x, a.y);
    f.y = pack_f16(a.z, a.w);
    f.z = pack_f16(b.x, b.y);
    f.w = pack_f16(b.z, b.w);
    ((uint4*)g_Wf)[(size_t)m * WU4 + gid] = f;
}

// ---------------------------------------------------------------------------
// fp16 single-MMA NT GEMM: C[m,n] = sum_k A[m,k]*W[n,k].
// CTA 128x128, 512 threads, 16 warps (4x4, warp 32x32), K staged 64/stage,
// cp.async double-buffered. PA: A fp16 pre-made (pure cp.async); else fp32
// converted in-loop. F16OUT: C -> fp16 scratch; else fp32 out.
// ---------------------------------------------------------------------------
#define GF_TILE_BYTES (128 * 64 * 2)            // 16 KB (f16 tile)
#define GF_BUF_BYTES (2 * GF_TILE_BYTES)        // A + B = 32 KB
#define GEMMF_SMEM (2 * GF_BUF_BYTES + 1024)
#define GK_STAGES 16

template <bool PA, bool F16OUT>
__device__ __forceinline__ void gemm_f16_body(
    const float* __restrict__ A, const unsigned* __restrict__ Af,
    const unsigned* __restrict__ Wf,
    float* __restrict__ C, unsigned* __restrict__ Cf) {
    extern __shared__ char dyn_raw[];
    char* dynb = (char*)(((unsigned long long)(size_t)dyn_raw + 1023ull) &
                         ~1023ull);
    const unsigned sbase = smem_u32(dynb);

    const int tid = threadIdx.x;
    const int wid = tid >> 5;
    const int lane = tid & 31;
    const int m0 = blockIdx.y * 128;
    const int n0 = blockIdx.x * 128;

    const float4* A4 = (const float4*)A;

    const int rb = tid >> 3;      // 0..63
    const int cc = tid & 7;

    const int wm = (wid >> 2) * 32;
    const int wn = (wid & 3) * 32;
    const int arow = lane & 15;
    const unsigned ahi = (unsigned)(lane >> 4);
    const unsigned axor = (unsigned)((arow & 7) << 4);
    const int brow = (lane & 7) + ((lane >> 4) << 3);
    const unsigned bxor = (unsigned)((brow & 7) << 4);
    const unsigned bhi = (unsigned)((lane >> 3) & 1);

    float d[2][4][4];
#pragma unroll
    for (int i = 0; i < 2; i++)
#pragma unroll
        for (int j = 0; j < 4; j++)
#pragma unroll
            for (int e = 0; e < 4; e++) d[i][j][e] = 0.0f;

    float4 ra[2][2];

#define FBUF(b) (dynb + (b) * GF_BUF_BYTES)

#define GF_LDGA(s)                                                         \
    do { if (!PA) {                                                        \
        _Pragma("unroll")                                                  \
        for (int i = 0; i < 2; i++) {                                      \
            const size_t ga =                                              \
                (size_t)(m0 + rb + 64 * i) * 256 + (s) * 16 + cc * 2;      \
            ra[i][0] = A4[ga];                                             \
            ra[i][1] = A4[ga + 1];                                         \
        } } } while (0)

#define GF_STSA(b)                                                         \
    do { if (!PA) {                                                        \
        char* Ap = FBUF(b);                                                \
        _Pragma("unroll")                                                  \
        for (int i = 0; i < 2; i++) {                                      \
            const int r = rb + 64 * i;                                     \
            const unsigned sw = (unsigned)(r * 128) +                      \
                (((unsigned)cc ^ (unsigned)(r & 7)) << 4);                 \
            uint4 f;                                                       \
            f.x = pack_f16(ra[i][0].x, ra[i][0].y);                        \
            f.y = pack_f16(ra[i][0].z, ra[i][0].w);                        \
            f.z = pack_f16(ra[i][1].x, ra[i][1].y);                        \
            f.w = pack_f16(ra[i][1].z, ra[i][1].w);                        \
            *(uint4*)(Ap + sw) = f;                                        \
        } } } while (0)

#define GF_CPA(s, b)                                                       \
    do { if (PA) {                                                         \
        _Pragma("unroll")                                                  \
        for (int i = 0; i < 2; i++) {                                      \
            const int idx = tid + 512 * i;                                 \
            const int r2 = idx >> 3, c2 = idx & 7;                         \
            cp_async16(FBUF(b) + r2 * 128 +                                \
                           (((unsigned)c2 ^ (unsigned)(r2 & 7)) << 4),     \
                       Af + (size_t)(m0 + r2) * DM2 + (s) * 32 + c2 * 4);  \
        } } } while (0)

#define GF_CPB(s, b)                                                       \
    do {                                                                   \
        _Pragma("unroll")                                                  \
        for (int i = 0; i < 2; i++) {                                      \
            const int idx = tid + 512 * i;                                 \
            const int r2 = idx >> 3, c2 = idx & 7;                         \
            cp_async16(FBUF(b) + GF_TILE_BYTES + r2 * 128 +                \
                           (((unsigned)c2 ^ (unsigned)(r2 & 7)) << 4),     \
                       Wf + (size_t)(n0 + r2) * DM2 + (s) * 32 + c2 * 4);  \
        } } while (0)

    GF_LDGA(0);
    GF_CPA(0, 0);
    GF_CPB(0, 0);
    cp_commit();
    GF_STSA(0);
    GF_LDGA(1);

    for (int s = 0; s < GK_STAGES; s++) {
        const int cur = s & 1;
        if (s + 1 < GK_STAGES) {
            GF_CPA(s + 1, cur ^ 1);
            GF_CPB(s + 1, cur ^ 1);
            cp_commit();
            GF_STSA(cur ^ 1);
            if (s + 2 < GK_STAGES) GF_LDGA(s + 2);
            cp_wait1();
        } else {
            cp_wait0();
        }
        __syncthreads();

        const unsigned bo = sbase + (unsigned)cur * GF_BUF_BYTES;
        const unsigned sA = bo;
        const unsigned sB = bo + GF_TILE_BYTES;
#pragma unroll
        for (int ks = 0; ks < 4; ks++) {
            unsigned bf[2][4];
#pragma unroll
            for (int j2 = 0; j2 < 2; j2++) {
                const unsigned roff =
                    (unsigned)(wn + 16 * j2 + brow) * 128 +
                    ((((unsigned)(2 * ks) + bhi) << 4) ^ bxor);
                ldmx4(bf[j2], sB + roff);
            }
#pragma unroll
            for (int i = 0; i < 2; i++) {
                const unsigned aoff =
                    (unsigned)(wm + 16 * i + arow) * 128 +
                    ((((unsigned)(2 * ks) + ahi) << 4) ^ axor);
                unsigned af[4];
                ldmx4(af, sA + aoff);
#pragma unroll
                for (int j = 0; j < 4; j++)
                    mma_f16(d[i][j], af, bf[j >> 1][(j & 1) * 2],
                            bf[j >> 1][(j & 1) * 2 + 1]);
            }
        }
        __syncthreads();
    }
#undef GF_LDGA
#undef GF_STSA
#undef GF_CPA
#undef GF_CPB
#undef FBUF

    // ---- epilogue ----
    const int r0 = m0 + wm + (lane >> 2);
    const int cb = n0 + wn + 2 * (lane & 3);
    if (F16OUT) {
#pragma unroll
        for (int i = 0; i < 2; i++)
#pragma unroll
            for (int j = 0; j < 4; j++) {
                const unsigned p0 = pack_f16(d[i][j][0], d[i][j][1]);
                const unsigned p1 = pack_f16(d[i][j][2], d[i][j][3]);
                const size_t idx =
                    (size_t)(r0 + 16 * i) * DM2 + (cb >> 1) + 4 * j;
                Cf[idx] = p0;
                Cf[idx + 8 * DM2] = p1;
            }
    } else {
        float* Cbase = C + (size_t)r0 * DMODEL + cb;
#pragma unroll
        for (int i = 0; i < 2; i++)
#pragma unroll
            for (int j = 0; j < 4; j++) {
                *(float2*)(Cbase + (size_t)(16 * i) * DMODEL + 8 * j) =
                    make_float2(d[i][j][0], d[i][j][1]);
                *(float2*)(Cbase + (size_t)(16 * i + 8) * DMODEL + 8 * j) =
                    make_float2(d[i][j][2], d[i][j][3]);
            }
    }
}

__global__ void __launch_bounds__(512, 1)
mha_gemm_qkv_f16(const float* __restrict__ q, const float* __restrict__ k,
                 const float* __restrict__ v) {
    const int z = blockIdx.z;
    const float* A = (z == 0) ? q : (z == 1) ? k : v;
    const unsigned* Wf = g_Wf + (size_t)z * DMODEL * DM2;
    unsigned* Cf = (z == 0) ? g_Qf : (z == 1) ? g_Kf : g_Vf;
    gemm_f16_body<false, true>(A, nullptr, Wf, nullptr, Cf);
}

__global__ void __launch_bounds__(512, 1)
mha_gemm_out_f16(float* __restrict__ out) {
    const unsigned* Wf = g_Wf + (size_t)3 * DMODEL * DM2;
    gemm_f16_body<true, false>(nullptr, g_Xf, Wf, out, nullptr);
}

// ---------------------------------------------------------------------------
// fp16 single-pass tensor-core flash attention (verified R14 core);
// epilogue now writes X as fp16 (single array).
// ---------------------------------------------------------------------------
#define ATT_BM 128
#define ATT_BN 64
#define ATT_TILE_B (ATT_BN * 128)            // 8 KB: 64 rows x 128B fp16
#define ATT_BUF_B (2 * ATT_TILE_B)           // Kf + Vf = 16 KB per buffer
#define ATT_SMEM (2 * ATT_BUF_B + 1024)      // ~33 KB

__global__ void __launch_bounds__(256)
mha_flash_attn_tc(const int* __restrict__ mask) {
    extern __shared__ char att_raw[];
    char* base = (char*)(((unsigned long long)(size_t)att_raw + 1023ull) &
                         ~1023ull);
    const unsigned sbase = smem_u32(base);

    const int tid = threadIdx.x;
    const int wid = tid >> 5;
    const int lane = tid & 31;
    const int q0 = blockIdx.x * ATT_BM;
    const int bh = blockIdx.y;
    const int b = bh >> 4;
    const int h = bh & 15;

    // ---- prologue: K/V tile 0 -> buf0; Q -> buf1 region ----
#pragma unroll
    for (int i = 0; i < 4; i++) {
        const int idx = tid + 256 * i;
        const int t = idx >> 9;                 // 0: K, 1: V
        const int idx2 = idx & 511;
        const int r = idx2 >> 3, cc = idx2 & 7;
        const unsigned* src = t ? g_Vf : g_Kf;
        const size_t gi = (size_t)(b * SEQ + r) * DM2 + h * 32 + cc * 4;
        char* dst = base + t * ATT_TILE_B + r * 128 + ((cc ^ (r & 7)) << 4);
        cp_async16(dst, src + gi);
    }
#pragma unroll
    for (int i = 0; i < 4; i++) {
        const int idx = tid + 256 * i;
        const int r = idx >> 3, cc = idx & 7;
        const size_t gi = (size_t)(b * SEQ + q0 + r) * DM2 + h * 32 + cc * 4;
        char* dst = base + ATT_BUF_B + r * 128 + ((cc ^ (r & 7)) << 4);
        cp_async16(dst, g_Qf + gi);
    }
    cp_commit();
    cp_wait0();
    __syncthreads();

    // ---- Q fragments (registers, whole kernel) ----
    unsigned qf[4][4];
    {
        const int arow = lane & 15;
        const unsigned ahi = (unsigned)(lane >> 4);
        const int row = 16 * wid + arow;
#pragma unroll
        for (int kk = 0; kk < 4; kk++) {
            const unsigned ch = 2 * (unsigned)kk + ahi;
            const unsigned off =
                (unsigned)(row * 128) + ((ch ^ (unsigned)(row & 7)) << 4);
            ldmx4(qf[kk], sbase + ATT_BUF_B + off);
        }
    }
    __syncthreads();

    float o[8][4];
#pragma unroll
    for (int j = 0; j < 8; j++)
#pragma unroll
        for (int e = 0; e < 4; e++) o[j][e] = 0.0f;
    float m0 = -1e30f, m1 = -1e30f, l0 = 0.0f, l1 = 0.0f;

    const int grow = q0 + 16 * wid + (lane >> 2);
    const int* mrow0 = mask + ((size_t)b * SEQ + grow) * SEQ;
    const int* mrow1 = mrow0 + 8 * SEQ;

    const int brow = (lane & 7) + ((lane >> 4) << 3);
    const unsigned bxor = (unsigned)((brow & 7) << 4);
    const unsigned bhi = (unsigned)((lane >> 3) & 1);
    const int vtt = lane >> 3;
    const int vrow_lo = ((vtt & 1) << 3) + (lane & 7);
    const unsigned vch_add = (unsigned)(vtt >> 1);

    for (int n = 0; n < SEQ / ATT_BN; n++) {
        const int j0 = n * ATT_BN;
        const int cur = n & 1;
        if (n > 0) {
            cp_wait0();
            __syncthreads();
        }
        if (n + 1 < SEQ / ATT_BN) {
            char* bufn = base + (cur ^ 1) * ATT_BUF_B;
            const int jn = j0 + ATT_BN;
#pragma unroll
            for (int i = 0; i < 4; i++) {
                const int idx = tid + 256 * i;
                const int t = idx >> 9;
                const int idx2 = idx & 511;
                const int r = idx2 >> 3, cc = idx2 & 7;
                const unsigned* src = t ? g_Vf : g_Kf;
                const size_t gi =
                    (size_t)(b * SEQ + jn + r) * DM2 + h * 32 + cc * 4;
                char* dst =
                    bufn + t * ATT_TILE_B + r * 128 + ((cc ^ (r & 7)) << 4);
                cp_async16(dst, src + gi);
            }
            cp_commit();
        }

        const unsigned sKf = sbase + (unsigned)cur * ATT_BUF_B;
        const unsigned sVf = sKf + ATT_TILE_B;

        // ---- S = Q.K^T ----
        float c[8][4];
#pragma unroll
        for (int j = 0; j < 8; j++)
#pragma unroll
            for (int e = 0; e < 4; e++) c[j][e] = 0.0f;

#pragma unroll
        for (int ks = 0; ks < 4; ks++) {
#pragma unroll
            for (int j2 = 0; j2 < 4; j2++) {
                const int kr = 16 * j2 + brow;
                const unsigned off = (unsigned)(kr * 128) +
                    ((((unsigned)(2 * ks) + bhi) << 4) ^ bxor);
                unsigned kb[4];
                ldmx4(kb, sKf + off);
                mma_f16(c[2 * j2],     qf[ks], kb[0], kb[1]);
                mma_f16(c[2 * j2 + 1], qf[ks], kb[2], kb[3]);
            }
        }

        // ---- scale + mask ----
        const int mcol = j0 + 2 * (lane & 3);
#pragma unroll
        for (int j = 0; j < 8; j++) {
            const int2 mv0 = *(const int2*)(mrow0 + mcol + 8 * j);
            const int2 mv1 = *(const int2*)(mrow1 + mcol + 8 * j);
            c[j][0] = mv0.x ? c[j][0] * 0.125f : -1e9f;
            c[j][1] = mv0.y ? c[j][1] * 0.125f : -1e9f;
            c[j][2] = mv1.x ? c[j][2] * 0.125f : -1e9f;
            c[j][3] = mv1.y ? c[j][3] * 0.125f : -1e9f;
        }

        // ---- row max ----
        float t0 = -1e30f, t1 = -1e30f;
#pragma unroll
        for (int j = 0; j < 8; j++) {
            t0 = fmaxf(t0, fmaxf(c[j][0], c[j][1]));
            t1 = fmaxf(t1, fmaxf(c[j][2], c[j][3]));
        }
        t0 = fmaxf(t0, __shfl_xor_sync(0xffffffffu, t0, 1));
        t0 = fmaxf(t0, __shfl_xor_sync(0xffffffffu, t0, 2));
        t1 = fmaxf(t1, __shfl_xor_sync(0xffffffffu, t1, 1));
        t1 = fmaxf(t1, __shfl_xor_sync(0xffffffffu, t1, 2));

        const float mn0 = fmaxf(m0, t0);
        const float mn1 = fmaxf(m1, t1);
        const float al0 = __expf(m0 - mn0);
        const float al1 = __expf(m1 - mn1);
        m0 = mn0; m1 = mn1;
        l0 *= al0; l1 *= al1;
#pragma unroll
        for (int j = 0; j < 8; j++) {
            o[j][0] *= al0; o[j][1] *= al0;
            o[j][2] *= al1; o[j][3] *= al1;
        }

        // ---- exponentiate ----
#pragma unroll
        for (int j = 0; j < 8; j++) {
            c[j][0] = __expf(c[j][0] - m0);
            c[j][1] = __expf(c[j][1] - m0);
            c[j][2] = __expf(c[j][2] - m1);
            c[j][3] = __expf(c[j][3] - m1);
            l0 += c[j][0] + c[j][1];
            l1 += c[j][2] + c[j][3];
        }

        // ---- O += P.V ----
#pragma unroll
        for (int kk = 0; kk < 4; kk++) {
            unsigned paf[4];
            paf[0] = pack_f16(c[2 * kk][0],     c[2 * kk][1]);
            paf[1] = pack_f16(c[2 * kk][2],     c[2 * kk][3]);
            paf[2] = pack_f16(c[2 * kk + 1][0], c[2 * kk + 1][1]);
            paf[3] = pack_f16(c[2 * kk + 1][2], c[2 * kk + 1][3]);
#pragma unroll
            for (int j2 = 0; j2 < 4; j2++) {
                const int vr = 16 * kk + vrow_lo;
                const unsigned ch = 2 * (unsigned)j2 + vch_add;
                const unsigned off = (unsigned)(vr * 128) +
                    ((ch ^ (unsigned)(vr & 7)) << 4);
                unsigned vb[4];
                ldmx4t(vb, sVf + off);
                mma_f16(o[2 * j2],     paf, vb[0], vb[1]);
                mma_f16(o[2 * j2 + 1], paf, vb[2], vb[3]);
            }
        }
    }

    // ---- finalize: normalize, write X as fp16 ----
    l0 += __shfl_xor_sync(0xffffffffu, l0, 1);
    l0 += __shfl_xor_sync(0xffffffffu, l0, 2);
    l1 += __shfl_xor_sync(0xffffffffu, l1, 1);
    l1 += __shfl_xor_sync(0xffffffffu, l1, 2);
    const float inv0 = 1.0f / l0;
    const float inv1 = 1.0f / l1;

    const size_t xrow = (size_t)(b * SEQ + grow) * DM2 + h * 32 + (lane & 3);
#pragma unroll
    for (int j = 0; j < 8; j++) {
        g_Xf[xrow + 4 * j] = pack_f16(o[j][0] * inv0, o[j][1] * inv0);
        g_Xf[xrow + 8 * DM2 + 4 * j] = pack_f16(o[j][2] * inv1, o[j][3] * inv1);
    }
}

// ---------------------------------------------------------------------------
// Launch
// Inputs (metadata order): q, k, v, w_q, w_k, w_v, w_o, mask
// ---------------------------------------------------------------------------
extern "C" void kernel_launch(void* const* d_in, const int* in_sizes, int n_in,
                              void* d_out, int out_size) {
    const float* q  = (const float*)d_in[0];
    const float* k  = (const float*)d_in[1];
    const float* v  = (const float*)d_in[2];
    const float* wq = (const float*)d_in[3];
    const float* wk = (const float*)d_in[4];
    const float* wv = (const float*)d_in[5];
    const float* wo = (const float*)d_in[6];
    const int* mask = (const int*)d_in[7];
    float* out = (float*)d_out;

    cudaFuncSetAttribute(mha_gemm_qkv_f16,
                         cudaFuncAttributeMaxDynamicSharedMemorySize,
                         GEMMF_SMEM);
    cudaFuncSetAttribute(mha_gemm_out_f16,
                         cudaFuncAttributeMaxDynamicSharedMemorySize,
                         GEMMF_SMEM);
    cudaFuncSetAttribute(mha_flash_attn_tc,
                         cudaFuncAttributeMaxDynamicSharedMemorySize, ATT_SMEM);

    // 0) weight prep: all four weights -> fp16
    dim3 gw(512, 4);
    presplit_w<<<gw, 256>>>(wq, wk, wv, wo);

    // 1) Q/K/V projections: fp16 single-MMA
    dim3 gqkv(DMODEL / 128, MROWS / 128, 3);
    mha_gemm_qkv_f16<<<gqkv, 512, GEMMF_SMEM>>>(q, k, v);

    // 2) fp16 flash attention (writes X fp16)
    dim3 gatt(SEQ / ATT_BM, BATCH * NHEAD);
    mha_flash_attn_tc<<<gatt, 256, ATT_SMEM>>>(mask);

    // 3) output projection: fp16 single-MMA
    dim3 gout(DMODEL / 128, MROWS / 128, 1);
    mha_gemm_out_f16<<<gout, 512, GEMMF_SMEM>>>(out);
}